// round 6
// baseline (speedup 1.0000x reference)
#include <cuda_runtime.h>
#include <cuda_bf16.h>

#define N_NODES 100000
#define N_EDGES 1600000
#define D_IN    64
#define D_H     128
#define D_M     256
#define D_OUT   40

// ---------------- device-global scratch --------------------------------------
__device__ __align__(16) float g_agg1[(size_t)N_NODES * D_IN];   // 25.6 MB
__device__ __align__(16) float g_agg2[(size_t)N_NODES * D_H];    // 51.2 MB
__device__ __align__(16) float g_cnt [N_NODES];
__device__ __align__(16) __nv_bfloat16 g_h1hi[(size_t)N_NODES * D_H];
__device__ __align__(16) __nv_bfloat16 g_h1lo[(size_t)N_NODES * D_H];
__device__ __align__(16) __nv_bfloat16 g_h2hi[(size_t)N_NODES * D_H];
__device__ __align__(16) __nv_bfloat16 g_h2lo[(size_t)N_NODES * D_H];
__device__ __align__(16) __nv_bfloat16 g_h3hi[(size_t)N_NODES * D_M];
__device__ __align__(16) __nv_bfloat16 g_h3lo[(size_t)N_NODES * D_M];

// ---------------- helpers ----------------------------------------------------
__device__ __forceinline__ void red_add_v4(float* p, float4 v) {
    asm volatile("red.global.add.v4.f32 [%0], {%1,%2,%3,%4};"
                 :: "l"(p), "f"(v.x), "f"(v.y), "f"(v.z), "f"(v.w) : "memory");
}
__device__ __forceinline__ float sigmoidf_(float x) {
    return 1.0f / (1.0f + __expf(-x));
}
__device__ __forceinline__ void split2(float x, __nv_bfloat16& hi, __nv_bfloat16& lo) {
    hi = __float2bfloat16(x);
    lo = __float2bfloat16(x - __bfloat162float(hi));
}
__device__ __forceinline__ unsigned pack_bf2(__nv_bfloat16 a, __nv_bfloat16 b) {
    return (unsigned)__bfloat16_as_ushort(a) | ((unsigned)__bfloat16_as_ushort(b) << 16);
}
__device__ __forceinline__ float2 bf2f2(unsigned u) {
    __nv_bfloat162 b = *(__nv_bfloat162*)&u;
    return __bfloat1622float2(b);
}
__device__ __forceinline__ unsigned smem_u32(const void* p) {
    return (unsigned)__cvta_generic_to_shared(p);
}

__device__ __forceinline__ void mma_bf16(float c[4], const unsigned a[4],
                                         unsigned b0, unsigned b1) {
    asm volatile("mma.sync.aligned.m16n8k16.row.col.f32.bf16.bf16.f32 "
                 "{%0,%1,%2,%3}, {%4,%5,%6,%7}, {%8,%9}, {%0,%1,%2,%3};"
                 : "+f"(c[0]), "+f"(c[1]), "+f"(c[2]), "+f"(c[3])
                 : "r"(a[0]), "r"(a[1]), "r"(a[2]), "r"(a[3]), "r"(b0), "r"(b1));
}
__device__ __forceinline__ void ldsm4(unsigned d[4], unsigned p) {
    asm volatile("ldmatrix.sync.aligned.m8n8.x4.shared.b16 {%0,%1,%2,%3}, [%4];"
                 : "=r"(d[0]), "=r"(d[1]), "=r"(d[2]), "=r"(d[3]) : "r"(p));
}

// one k16 step of a 32x(NF*8) warp tile, ldmatrix fragments, hi/lo compensation.
// The 3 compensation passes are issued as separated sweeps so each accumulator
// is only revisited after 2*NF independent HMMAs (breaks acc RAW chains).
// NF must be even.
template<int NF>
__device__ __forceinline__ void mma_step(
    float (&acc)[2][NF][4],
    unsigned aHi, unsigned aLo, int KPa,     // shared-space byte addresses
    unsigned wHi, unsigned wLo, int KPw,
    int m0, int n0, int kbA, int kbW, int lane)
{
    int lr = lane & 15, lc = lane >> 4;
    unsigned ah[2][4], al[2][4];
#pragma unroll
    for (int mf = 0; mf < 2; mf++) {
        unsigned off = (unsigned)(((m0 + mf * 16 + lr) * KPa + kbA + lc * 8) * 2);
        ldsm4(ah[mf], aHi + off);
        ldsm4(al[mf], aLo + off);
    }
    unsigned th[NF / 2][4], tl[NF / 2][4];
#pragma unroll
    for (int p = 0; p < NF / 2; p++) {
        unsigned off = (unsigned)(((n0 + p * 16 + lr) * KPw + kbW + lc * 8) * 2);
        ldsm4(th[p], wHi + off);
        ldsm4(tl[p], wLo + off);
    }
    // pass 1: hi * hi  (all 2*NF targets, independent)
#pragma unroll
    for (int p = 0; p < NF / 2; p++)
#pragma unroll
        for (int mf = 0; mf < 2; mf++) {
            mma_bf16(acc[mf][2 * p    ], ah[mf], th[p][0], th[p][2]);
            mma_bf16(acc[mf][2 * p + 1], ah[mf], th[p][1], th[p][3]);
        }
    // pass 2: hi * lo
#pragma unroll
    for (int p = 0; p < NF / 2; p++)
#pragma unroll
        for (int mf = 0; mf < 2; mf++) {
            mma_bf16(acc[mf][2 * p    ], ah[mf], tl[p][0], tl[p][2]);
            mma_bf16(acc[mf][2 * p + 1], ah[mf], tl[p][1], tl[p][3]);
        }
    // pass 3: lo * hi
#pragma unroll
    for (int p = 0; p < NF / 2; p++)
#pragma unroll
        for (int mf = 0; mf < 2; mf++) {
            mma_bf16(acc[mf][2 * p    ], al[mf], th[p][0], th[p][2]);
            mma_bf16(acc[mf][2 * p + 1], al[mf], th[p][1], th[p][3]);
        }
}

// ---------------- zero accumulators ------------------------------------------
__global__ void zero_kernel() {
    const unsigned T1 = N_NODES * D_IN / 4;
    const unsigned T2 = N_NODES * D_H / 4;
    const unsigned T3 = N_NODES / 4;
    unsigned i = blockIdx.x * blockDim.x + threadIdx.x;
    unsigned stride = gridDim.x * blockDim.x;
    float4 z = make_float4(0.f, 0.f, 0.f, 0.f);
    for (unsigned j = i; j < T1; j += stride) ((float4*)g_agg1)[j] = z;
    for (unsigned j = i; j < T2; j += stride) ((float4*)g_agg2)[j] = z;
    for (unsigned j = i; j < T3; j += stride) ((float4*)g_cnt )[j] = z;
}

// ---------------- scatters ---------------------------------------------------
__global__ void scatter1_kernel(const float* __restrict__ feat,
                                const int* __restrict__ ei) {
    unsigned gid = blockIdx.x * blockDim.x + threadIdx.x;
    if (gid >= (unsigned)N_EDGES * 16u) return;
    unsigned e = gid >> 4, p = gid & 15u;
    int s = __ldg(&ei[e]);
    int d = __ldg(&ei[N_EDGES + e]);
    if ((unsigned)s >= (unsigned)N_NODES || (unsigned)d >= (unsigned)N_NODES) return;
    float4 v = __ldg((const float4*)(feat + (size_t)s * D_IN) + p);
    red_add_v4(g_agg1 + (size_t)d * D_IN + p * 4, v);
    if (p == 0) atomicAdd(&g_cnt[d], 1.0f);
}

__global__ void scatter2_kernel(const int* __restrict__ ei) {
    unsigned gid = blockIdx.x * blockDim.x + threadIdx.x;
    if (gid >= (unsigned)N_EDGES * 32u) return;
    unsigned e = gid >> 5, p = gid & 31u;
    int s = __ldg(&ei[e]);
    int d = __ldg(&ei[N_EDGES + e]);
    if ((unsigned)s >= (unsigned)N_NODES || (unsigned)d >= (unsigned)N_NODES) return;
    size_t off = (size_t)s * D_H + p * 4;
    uint2 vh = *(const uint2*)(g_h1hi + off);
    uint2 vl = *(const uint2*)(g_h1lo + off);
    float2 a = bf2f2(vh.x), b = bf2f2(vh.y), c = bf2f2(vl.x), dd = bf2f2(vl.y);
    float4 v = make_float4(a.x + c.x, a.y + c.y, b.x + dd.x, b.y + dd.y);
    red_add_v4(g_agg2 + (size_t)d * D_H + p * 4, v);
}

// ============================================================================
// Layer-1: h1 = sigmoid([feat | agg1/cnt] @ W1 + b1)   (M=128/blk, N=128, K=128)
// ============================================================================
#define KP128 136
#define L1_SMEM ((4 * 128 * KP128) * 2 + 128 * 4)
__global__ void __launch_bounds__(256, 1)
l1_mma_kernel(const float* __restrict__ feat,
              const float* __restrict__ W1, const float* __restrict__ b1) {
    extern __shared__ unsigned char smraw[];
    __nv_bfloat16* Ahi = (__nv_bfloat16*)smraw;
    __nv_bfloat16* Alo = Ahi + 128 * KP128;
    __nv_bfloat16* Whi = Alo + 128 * KP128;
    __nv_bfloat16* Wlo = Whi + 128 * KP128;
    float* rcpS = (float*)(Wlo + 128 * KP128);
    int tid = threadIdx.x;
    int node0 = blockIdx.x * 128;

    for (int r = tid; r < 128; r += 256) {
        int gn = node0 + r;
        rcpS[r] = (gn < N_NODES) ? 1.0f / fmaxf(__ldg(&g_cnt[gn]), 1.0f) : 0.f;
    }
    __syncthreads();

    for (int i = tid; i < 128 * 128; i += 256) {   // W1: [128][128] -> Wt[n][k]
        int k = i >> 7, n = i & 127;
        __nv_bfloat16 h, l; split2(__ldg(&W1[i]), h, l);
        Whi[n * KP128 + k] = h; Wlo[n * KP128 + k] = l;
    }
    for (int i = tid; i < 128 * 128; i += 256) {   // A = [feat | agg1/cnt]
        int r = i >> 7, c = i & 127;
        int gn = node0 + r;
        float x = 0.f;
        if (gn < N_NODES)
            x = (c < 64) ? __ldg(&feat[(size_t)gn * 64 + c])
                         : g_agg1[(size_t)gn * 64 + (c - 64)] * rcpS[r];
        __nv_bfloat16 h, l; split2(x, h, l);
        Ahi[r * KP128 + c] = h; Alo[r * KP128 + c] = l;
    }
    __syncthreads();

    unsigned uAhi = smem_u32(Ahi), uAlo = smem_u32(Alo);
    unsigned uWhi = smem_u32(Whi), uWlo = smem_u32(Wlo);
    int w = tid >> 5, lane = tid & 31, g = lane >> 2, t = lane & 3;
    int m0 = (w & 3) * 32, n0 = (w >> 2) * 64;
    float acc[2][8][4];
#pragma unroll
    for (int a = 0; a < 2; a++)
#pragma unroll
        for (int b = 0; b < 8; b++)
#pragma unroll
            for (int c = 0; c < 4; c++) acc[a][b][c] = 0.f;

#pragma unroll
    for (int ks = 0; ks < 8; ks++)
        mma_step<8>(acc, uAhi, uAlo, KP128, uWhi, uWlo, KP128,
                    m0, n0, ks * 16, ks * 16, lane);

#pragma unroll
    for (int mf = 0; mf < 2; mf++) {
        int r0 = node0 + m0 + mf * 16 + g;
#pragma unroll
        for (int nf = 0; nf < 8; nf++) {
            int col = n0 + nf * 8 + t * 2;
            float2 bv = *(const float2*)&b1[col];
            if (r0 < N_NODES) {
                float v0 = sigmoidf_(acc[mf][nf][0] + bv.x);
                float v1 = sigmoidf_(acc[mf][nf][1] + bv.y);
                __nv_bfloat16 h0, l0, h1, l1; split2(v0, h0, l0); split2(v1, h1, l1);
                size_t idx = (size_t)r0 * D_H + col;
                *(unsigned*)&g_h1hi[idx] = pack_bf2(h0, h1);
                *(unsigned*)&g_h1lo[idx] = pack_bf2(l0, l1);
            }
            if (r0 + 8 < N_NODES) {
                float v0 = sigmoidf_(acc[mf][nf][2] + bv.x);
                float v1 = sigmoidf_(acc[mf][nf][3] + bv.y);
                __nv_bfloat16 h0, l0, h1, l1; split2(v0, h0, l0); split2(v1, h1, l1);
                size_t idx = (size_t)(r0 + 8) * D_H + col;
                *(unsigned*)&g_h1hi[idx] = pack_bf2(h0, h1);
                *(unsigned*)&g_h1lo[idx] = pack_bf2(l0, l1);
            }
        }
    }
}

// ============================================================================
// Layer-2: h2 = sigmoid([h1 | agg2/cnt] @ W2 + b2)   (M=128/blk, N=128, K=256)
// ============================================================================
#define KP256 264
#define L2_SMEM ((2 * 128 * KP128 + 2 * 128 * KP256) * 2 + 128 * 4)
__global__ void __launch_bounds__(256, 1)
l2_mma_kernel(const float* __restrict__ W2, const float* __restrict__ b2) {
    extern __shared__ unsigned char smraw[];
    __nv_bfloat16* Ahi = (__nv_bfloat16*)smraw;            // [128][KP128] (k-chunk)
    __nv_bfloat16* Alo = Ahi + 128 * KP128;
    __nv_bfloat16* Whi = Alo + 128 * KP128;                // [128][KP256] full K
    __nv_bfloat16* Wlo = Whi + 128 * KP256;
    float* rcpS = (float*)(Wlo + 128 * KP256);
    int tid = threadIdx.x;
    int node0 = blockIdx.x * 128;

    for (int r = tid; r < 128; r += 256) {
        int gn = node0 + r;
        rcpS[r] = (gn < N_NODES) ? 1.0f / fmaxf(__ldg(&g_cnt[gn]), 1.0f) : 0.f;
    }
    for (int i = tid; i < 256 * 128; i += 256) {    // W2: [256][128] -> Wt[n][k]
        int k = i >> 7, n = i & 127;
        __nv_bfloat16 h, l; split2(__ldg(&W2[i]), h, l);
        Whi[n * KP256 + k] = h; Wlo[n * KP256 + k] = l;
    }
    for (int i = tid; i < 128 * 64; i += 256) {     // A chunk0 = copy of h1 hi/lo
        int r = i >> 6, c2 = (i & 63) * 2;
        int gn = node0 + r;
        unsigned vh = 0, vl = 0;
        if (gn < N_NODES) {
            vh = *(const unsigned*)&g_h1hi[(size_t)gn * D_H + c2];
            vl = *(const unsigned*)&g_h1lo[(size_t)gn * D_H + c2];
        }
        *(unsigned*)&Ahi[r * KP128 + c2] = vh;
        *(unsigned*)&Alo[r * KP128 + c2] = vl;
    }
    __syncthreads();

    unsigned uAhi = smem_u32(Ahi), uAlo = smem_u32(Alo);
    unsigned uWhi = smem_u32(Whi), uWlo = smem_u32(Wlo);
    int w = tid >> 5, lane = tid & 31, g = lane >> 2, t = lane & 3;
    int m0 = (w & 3) * 32, n0 = (w >> 2) * 64;
    float acc[2][8][4];
#pragma unroll
    for (int a = 0; a < 2; a++)
#pragma unroll
        for (int b = 0; b < 8; b++)
#pragma unroll
            for (int c = 0; c < 4; c++) acc[a][b][c] = 0.f;

#pragma unroll
    for (int ks = 0; ks < 8; ks++)
        mma_step<8>(acc, uAhi, uAlo, KP128, uWhi, uWlo, KP256,
                    m0, n0, ks * 16, ks * 16, lane);
    __syncthreads();

    for (int i = tid; i < 128 * 128; i += 256) {    // A chunk1 = agg2/cnt
        int r = i >> 7, c = i & 127;
        int gn = node0 + r;
        float x = (gn < N_NODES) ? g_agg2[(size_t)gn * D_H + c] * rcpS[r] : 0.f;
        __nv_bfloat16 h, l; split2(x, h, l);
        Ahi[r * KP128 + c] = h; Alo[r * KP128 + c] = l;
    }
    __syncthreads();

#pragma unroll
    for (int ks = 0; ks < 8; ks++)
        mma_step<8>(acc, uAhi, uAlo, KP128, uWhi, uWlo, KP256,
                    m0, n0, ks * 16, 128 + ks * 16, lane);

#pragma unroll
    for (int mf = 0; mf < 2; mf++) {
        int r0 = node0 + m0 + mf * 16 + g;
#pragma unroll
        for (int nf = 0; nf < 8; nf++) {
            int col = n0 + nf * 8 + t * 2;
            float2 bv = *(const float2*)&b2[col];
            if (r0 < N_NODES) {
                float v0 = sigmoidf_(acc[mf][nf][0] + bv.x);
                float v1 = sigmoidf_(acc[mf][nf][1] + bv.y);
                __nv_bfloat16 h0, l0, h1, l1; split2(v0, h0, l0); split2(v1, h1, l1);
                size_t idx = (size_t)r0 * D_H + col;
                *(unsigned*)&g_h2hi[idx] = pack_bf2(h0, h1);
                *(unsigned*)&g_h2lo[idx] = pack_bf2(l0, l1);
            }
            if (r0 + 8 < N_NODES) {
                float v0 = sigmoidf_(acc[mf][nf][2] + bv.x);
                float v1 = sigmoidf_(acc[mf][nf][3] + bv.y);
                __nv_bfloat16 h0, l0, h1, l1; split2(v0, h0, l0); split2(v1, h1, l1);
                size_t idx = (size_t)(r0 + 8) * D_H + col;
                *(unsigned*)&g_h2hi[idx] = pack_bf2(h0, h1);
                *(unsigned*)&g_h2lo[idx] = pack_bf2(l0, l1);
            }
        }
    }
}

// ============================================================================
// MLP-1: h3 = relu(h2 @ Wm1 + bm1)   (M=128/blk, N=256 in two 128-halves, K=128)
// ============================================================================
#define M1_SMEM ((4 * 128 * KP128) * 2)
__global__ void __launch_bounds__(256, 1)
m1_mma_kernel(const float* __restrict__ Wm1, const float* __restrict__ bm1) {
    extern __shared__ unsigned char smraw[];
    __nv_bfloat16* Ahi = (__nv_bfloat16*)smraw;
    __nv_bfloat16* Alo = Ahi + 128 * KP128;
    __nv_bfloat16* Whi = Alo + 128 * KP128;   // [128 n][KP128] per n-half
    __nv_bfloat16* Wlo = Whi + 128 * KP128;
    int tid = threadIdx.x;
    int node0 = blockIdx.x * 128;

    for (int i = tid; i < 128 * 64; i += 256) {     // A = copy of h2 hi/lo
        int r = i >> 6, c2 = (i & 63) * 2;
        int gn = node0 + r;
        unsigned vh = 0, vl = 0;
        if (gn < N_NODES) {
            vh = *(const unsigned*)&g_h2hi[(size_t)gn * D_H + c2];
            vl = *(const unsigned*)&g_h2lo[(size_t)gn * D_H + c2];
        }
        *(unsigned*)&Ahi[r * KP128 + c2] = vh;
        *(unsigned*)&Alo[r * KP128 + c2] = vl;
    }

    unsigned uAhi = smem_u32(Ahi), uAlo = smem_u32(Alo);
    unsigned uWhi = smem_u32(Whi), uWlo = smem_u32(Wlo);
    int w = tid >> 5, lane = tid & 31, g = lane >> 2, t = lane & 3;
    int m0 = (w & 3) * 32, n0 = (w >> 2) * 64;

    for (int nb = 0; nb < 2; nb++) {
        if (nb) __syncthreads();
        for (int i = tid; i < 128 * 128; i += 256) {  // W half: cols nb*128..+128
            int k = i >> 7, n = i & 127;
            __nv_bfloat16 h, l; split2(__ldg(&Wm1[k * 256 + nb * 128 + n]), h, l);
            Whi[n * KP128 + k] = h; Wlo[n * KP128 + k] = l;
        }
        __syncthreads();

        float acc[2][8][4];
#pragma unroll
        for (int a = 0; a < 2; a++)
#pragma unroll
            for (int b = 0; b < 8; b++)
#pragma unroll
                for (int c = 0; c < 4; c++) acc[a][b][c] = 0.f;

#pragma unroll
        for (int ks = 0; ks < 8; ks++)
            mma_step<8>(acc, uAhi, uAlo, KP128, uWhi, uWlo, KP128,
                        m0, n0, ks * 16, ks * 16, lane);

#pragma unroll
        for (int mf = 0; mf < 2; mf++) {
            int r0 = node0 + m0 + mf * 16 + g;
#pragma unroll
            for (int nf = 0; nf < 8; nf++) {
                int col = nb * 128 + n0 + nf * 8 + t * 2;
                float2 bv = *(const float2*)&bm1[col];
                if (r0 < N_NODES) {
                    float v0 = fmaxf(acc[mf][nf][0] + bv.x, 0.f);
                    float v1 = fmaxf(acc[mf][nf][1] + bv.y, 0.f);
                    __nv_bfloat16 h0, l0, h1, l1; split2(v0, h0, l0); split2(v1, h1, l1);
                    size_t idx = (size_t)r0 * D_M + col;
                    *(unsigned*)&g_h3hi[idx] = pack_bf2(h0, h1);
                    *(unsigned*)&g_h3lo[idx] = pack_bf2(l0, l1);
                }
                if (r0 + 8 < N_NODES) {
                    float v0 = fmaxf(acc[mf][nf][2] + bv.x, 0.f);
                    float v1 = fmaxf(acc[mf][nf][3] + bv.y, 0.f);
                    __nv_bfloat16 h0, l0, h1, l1; split2(v0, h0, l0); split2(v1, h1, l1);
                    size_t idx = (size_t)(r0 + 8) * D_M + col;
                    *(unsigned*)&g_h3hi[idx] = pack_bf2(h0, h1);
                    *(unsigned*)&g_h3lo[idx] = pack_bf2(l0, l1);
                }
            }
        }
    }
}

// ============================================================================
// MLP-2: out = h3 @ Wm2 + bm2   (M=256/blk, N=40(pad 48), K=256 in two chunks)
// ============================================================================
#define M2_SMEM ((2 * 256 * KP128 + 2 * 48 * KP256) * 2)
__global__ void __launch_bounds__(256, 1)
m2_mma_kernel(const float* __restrict__ Wm2, const float* __restrict__ bm2,
              float* __restrict__ out) {
    extern __shared__ unsigned char smraw[];
    __nv_bfloat16* Ahi = (__nv_bfloat16*)smraw;            // [256][KP128]
    __nv_bfloat16* Alo = Ahi + 256 * KP128;
    __nv_bfloat16* Whi = Alo + 256 * KP128;                // [48][KP256]
    __nv_bfloat16* Wlo = Whi + 48 * KP256;
    int tid = threadIdx.x;
    int node0 = blockIdx.x * 256;

    for (int i = tid; i < 48 * KP256 / 2; i += 256) {   // zero pad rows 40-47
        ((unsigned*)Whi)[i] = 0; ((unsigned*)Wlo)[i] = 0;
    }
    __syncthreads();
    for (int i = tid; i < 256 * 40; i += 256) {     // Wm2: [256][40] -> Wt[n][k]
        int k = i / 40, n = i % 40;
        __nv_bfloat16 h, l; split2(__ldg(&Wm2[i]), h, l);
        Whi[n * KP256 + k] = h; Wlo[n * KP256 + k] = l;
    }

    unsigned uAhi = smem_u32(Ahi), uAlo = smem_u32(Alo);
    unsigned uWhi = smem_u32(Whi), uWlo = smem_u32(Wlo);
    int w = tid >> 5, lane = tid & 31, g = lane >> 2, t = lane & 3;
    int m0 = w * 32, n0 = 0;
    float acc[2][6][4];
#pragma unroll
    for (int a = 0; a < 2; a++)
#pragma unroll
        for (int b = 0; b < 6; b++)
#pragma unroll
            for (int c = 0; c < 4; c++) acc[a][b][c] = 0.f;

    for (int kc = 0; kc < 2; kc++) {
        if (kc) __syncthreads();
        for (int i = tid; i < 256 * 64; i += 256) {  // A chunk = copy of h3 hi/lo
            int r = i >> 6, c2 = (i & 63) * 2;
            int gn = node0 + r;
            unsigned vh = 0, vl = 0;
            if (gn < N_NODES) {
                vh = *(const unsigned*)&g_h3hi[(size_t)gn * D_M + kc * 128 + c2];
                vl = *(const unsigned*)&g_h3lo[(size_t)gn * D_M + kc * 128 + c2];
            }
            *(unsigned*)&Ahi[r * KP128 + c2] = vh;
            *(unsigned*)&Alo[r * KP128 + c2] = vl;
        }
        __syncthreads();
#pragma unroll
        for (int ks = 0; ks < 8; ks++)
            mma_step<6>(acc, uAhi, uAlo, KP128, uWhi, uWlo, KP256,
                        m0, n0, ks * 16, kc * 128 + ks * 16, lane);
    }

#pragma unroll
    for (int mf = 0; mf < 2; mf++) {
        int r0 = node0 + m0 + mf * 16 + g;
#pragma unroll
        for (int nf = 0; nf < 5; nf++) {
            int col = nf * 8 + t * 2;
            float2 bv = *(const float2*)&bm2[col];
            if (r0 < N_NODES) {
                float2 o = make_float2(acc[mf][nf][0] + bv.x, acc[mf][nf][1] + bv.y);
                *(float2*)&out[(size_t)r0 * D_OUT + col] = o;
            }
            if (r0 + 8 < N_NODES) {
                float2 o = make_float2(acc[mf][nf][2] + bv.x, acc[mf][nf][3] + bv.y);
                *(float2*)&out[(size_t)(r0 + 8) * D_OUT + col] = o;
            }
        }
    }
}

// ---------------- launch -----------------------------------------------------
extern "C" void kernel_launch(void* const* d_in, const int* in_sizes, int n_in,
                              void* d_out, int out_size) {
    const float* feat = (const float*)d_in[0];
    const int*   ei   = (const int*)d_in[1];     // int32 (JAX x64 disabled)
    const float* W1   = (const float*)d_in[2];
    const float* b1   = (const float*)d_in[3];
    const float* W2   = (const float*)d_in[4];
    const float* b2   = (const float*)d_in[5];
    const float* Wm1  = (const float*)d_in[6];
    const float* bm1  = (const float*)d_in[7];
    const float* Wm2  = (const float*)d_in[8];
    const float* bm2  = (const float*)d_in[9];
    float* out = (float*)d_out;

    cudaFuncSetAttribute(l1_mma_kernel, cudaFuncAttributeMaxDynamicSharedMemorySize, L1_SMEM);
    cudaFuncSetAttribute(l2_mma_kernel, cudaFuncAttributeMaxDynamicSharedMemorySize, L2_SMEM);
    cudaFuncSetAttribute(m1_mma_kernel, cudaFuncAttributeMaxDynamicSharedMemorySize, M1_SMEM);
    cudaFuncSetAttribute(m2_mma_kernel, cudaFuncAttributeMaxDynamicSharedMemorySize, M2_SMEM);

    zero_kernel<<<2048, 256>>>();

    scatter1_kernel<<<((unsigned)N_EDGES * 16u + 255) / 256, 256>>>(feat, ei);
    l1_mma_kernel<<<(N_NODES + 127) / 128, 256, L1_SMEM>>>(feat, W1, b1);

    scatter2_kernel<<<((unsigned)N_EDGES * 32u + 255) / 256, 256>>>(ei);
    l2_mma_kernel<<<(N_NODES + 127) / 128, 256, L2_SMEM>>>(W2, b2);

    m1_mma_kernel<<<(N_NODES + 127) / 128, 256, M1_SMEM>>>(Wm1, bm1);
    m2_mma_kernel<<<(N_NODES + 255) / 256, 256, M2_SMEM>>>(Wm2, bm2, out);
}

// round 7
// speedup vs baseline: 1.4234x; 1.4234x over previous
#include <cuda_runtime.h>
#include <cuda_bf16.h>

#define N_NODES 100000
#define N_EDGES 1600000
#define D_IN    64
#define D_H     128
#define D_M     256
#define D_OUT   40
#define NB_SCAN 391   // ceil(N_NODES/256)

// ---------------- device-global scratch --------------------------------------
__device__ int g_cnt_i[N_NODES];          // degree histogram
__device__ int g_rs  [N_NODES];           // CSR row start (exclusive scan)
__device__ int g_wr  [N_NODES];           // fill cursors
__device__ int g_bsum[512];               // scan block sums
__device__ int g_adj [N_EDGES];           // CSR: src ids grouped by dst
__device__ __align__(16) __nv_bfloat16 g_a1hi[(size_t)N_NODES * D_IN];
__device__ __align__(16) __nv_bfloat16 g_a1lo[(size_t)N_NODES * D_IN];
__device__ __align__(16) __nv_bfloat16 g_a2hi[(size_t)N_NODES * D_H];
__device__ __align__(16) __nv_bfloat16 g_a2lo[(size_t)N_NODES * D_H];
__device__ __align__(16) __nv_bfloat16 g_h1hi[(size_t)N_NODES * D_H];
__device__ __align__(16) __nv_bfloat16 g_h1lo[(size_t)N_NODES * D_H];
__device__ __align__(16) __nv_bfloat16 g_h2hi[(size_t)N_NODES * D_H];
__device__ __align__(16) __nv_bfloat16 g_h2lo[(size_t)N_NODES * D_H];
__device__ __align__(16) __nv_bfloat16 g_h3hi[(size_t)N_NODES * D_M];
__device__ __align__(16) __nv_bfloat16 g_h3lo[(size_t)N_NODES * D_M];

// ---------------- helpers ----------------------------------------------------
__device__ __forceinline__ float sigmoidf_(float x) {
    return 1.0f / (1.0f + __expf(-x));
}
__device__ __forceinline__ void split2(float x, __nv_bfloat16& hi, __nv_bfloat16& lo) {
    hi = __float2bfloat16(x);
    lo = __float2bfloat16(x - __bfloat162float(hi));
}
__device__ __forceinline__ unsigned pack_bf2(__nv_bfloat16 a, __nv_bfloat16 b) {
    return (unsigned)__bfloat16_as_ushort(a) | ((unsigned)__bfloat16_as_ushort(b) << 16);
}
__device__ __forceinline__ float2 bf2f2(unsigned u) {
    __nv_bfloat162 b = *(__nv_bfloat162*)&u;
    return __bfloat1622float2(b);
}
__device__ __forceinline__ unsigned smem_u32(const void* p) {
    return (unsigned)__cvta_generic_to_shared(p);
}

__device__ __forceinline__ void mma_bf16(float c[4], const unsigned a[4],
                                         unsigned b0, unsigned b1) {
    asm volatile("mma.sync.aligned.m16n8k16.row.col.f32.bf16.bf16.f32 "
                 "{%0,%1,%2,%3}, {%4,%5,%6,%7}, {%8,%9}, {%0,%1,%2,%3};"
                 : "+f"(c[0]), "+f"(c[1]), "+f"(c[2]), "+f"(c[3])
                 : "r"(a[0]), "r"(a[1]), "r"(a[2]), "r"(a[3]), "r"(b0), "r"(b1));
}

// one k16 step of a 32x(NF*8) warp tile with hi/lo error compensation (R3 form)
template<int NF>
__device__ __forceinline__ void mma_step(
    float (&acc)[2][NF][4],
    const __nv_bfloat16* __restrict__ Ahi, const __nv_bfloat16* __restrict__ Alo, int KPa,
    const __nv_bfloat16* __restrict__ Whi, const __nv_bfloat16* __restrict__ Wlo, int KPw,
    int m0, int n0, int kbA, int kbW, int g, int t)
{
    unsigned ah[2][4], al[2][4];
#pragma unroll
    for (int mf = 0; mf < 2; mf++) {
        int r = m0 + mf * 16 + g;
        ah[mf][0] = *(const unsigned*)&Ahi[(r    ) * KPa + kbA     + t * 2];
        ah[mf][1] = *(const unsigned*)&Ahi[(r + 8) * KPa + kbA     + t * 2];
        ah[mf][2] = *(const unsigned*)&Ahi[(r    ) * KPa + kbA + 8 + t * 2];
        ah[mf][3] = *(const unsigned*)&Ahi[(r + 8) * KPa + kbA + 8 + t * 2];
        al[mf][0] = *(const unsigned*)&Alo[(r    ) * KPa + kbA     + t * 2];
        al[mf][1] = *(const unsigned*)&Alo[(r + 8) * KPa + kbA     + t * 2];
        al[mf][2] = *(const unsigned*)&Alo[(r    ) * KPa + kbA + 8 + t * 2];
        al[mf][3] = *(const unsigned*)&Alo[(r + 8) * KPa + kbA + 8 + t * 2];
    }
#pragma unroll
    for (int nf = 0; nf < NF; nf++) {
        int n = n0 + nf * 8 + g;
        unsigned bh0 = *(const unsigned*)&Whi[n * KPw + kbW     + t * 2];
        unsigned bh1 = *(const unsigned*)&Whi[n * KPw + kbW + 8 + t * 2];
        unsigned bl0 = *(const unsigned*)&Wlo[n * KPw + kbW     + t * 2];
        unsigned bl1 = *(const unsigned*)&Wlo[n * KPw + kbW + 8 + t * 2];
#pragma unroll
        for (int mf = 0; mf < 2; mf++) {
            mma_bf16(acc[mf][nf], ah[mf], bh0, bh1);
            mma_bf16(acc[mf][nf], ah[mf], bl0, bl1);
            mma_bf16(acc[mf][nf], al[mf], bh0, bh1);
        }
    }
}

// ---------------- CSR build --------------------------------------------------
__global__ void zero_cnt_kernel() {
    unsigned i = blockIdx.x * blockDim.x + threadIdx.x;
    if (i < N_NODES) g_cnt_i[i] = 0;
}
__global__ void hist_kernel(const int* __restrict__ ei) {
    unsigned e = blockIdx.x * blockDim.x + threadIdx.x;
    if (e >= N_EDGES) return;
    int s = __ldg(&ei[e]);
    int d = __ldg(&ei[N_EDGES + e]);
    if ((unsigned)s >= (unsigned)N_NODES || (unsigned)d >= (unsigned)N_NODES) return;
    atomicAdd(&g_cnt_i[d], 1);
}
__global__ void scan1_kernel() {                 // per-256-block exclusive scan
    __shared__ int sm[256];
    int t = threadIdx.x, b = blockIdx.x;
    int i = b * 256 + t;
    int v = (i < N_NODES) ? g_cnt_i[i] : 0;
    sm[t] = v; __syncthreads();
    for (int off = 1; off < 256; off <<= 1) {
        int x = (t >= off) ? sm[t - off] : 0;
        __syncthreads(); sm[t] += x; __syncthreads();
    }
    if (i < N_NODES) g_rs[i] = sm[t] - v;
    if (t == 255) g_bsum[b] = sm[255];
}
__global__ void scan2_kernel() {                 // exclusive scan of block sums
    __shared__ int sm[512];
    int t = threadIdx.x;
    int v = (t < NB_SCAN) ? g_bsum[t] : 0;
    sm[t] = v; __syncthreads();
    for (int off = 1; off < 512; off <<= 1) {
        int x = (t >= off) ? sm[t - off] : 0;
        __syncthreads(); sm[t] += x; __syncthreads();
    }
    if (t < NB_SCAN) g_bsum[t] = sm[t] - v;
}
__global__ void scan3_kernel() {                 // add offsets, init cursors
    int i = blockIdx.x * blockDim.x + threadIdx.x;
    if (i >= N_NODES) return;
    int v = g_rs[i] + g_bsum[blockIdx.x];
    g_rs[i] = v;
    g_wr[i] = v;
}
__global__ void fill_kernel(const int* __restrict__ ei) {
    unsigned e = blockIdx.x * blockDim.x + threadIdx.x;
    if (e >= N_EDGES) return;
    int s = __ldg(&ei[e]);
    int d = __ldg(&ei[N_EDGES + e]);
    if ((unsigned)s >= (unsigned)N_NODES || (unsigned)d >= (unsigned)N_NODES) return;
    g_adj[atomicAdd(&g_wr[d], 1)] = s;
}

// ---------------- gather-reduce (warp per node), fused mean + split ----------
__global__ void gather1_kernel(const float* __restrict__ feat) {
    int warp = (blockIdx.x * blockDim.x + threadIdx.x) >> 5;
    int lane = threadIdx.x & 31;
    if (warp >= N_NODES) return;
    int deg = g_cnt_i[warp], start = g_rs[warp];
    float2 acc = make_float2(0.f, 0.f);
    for (int j = 0; j < deg; j++) {
        int s = __ldg(&g_adj[start + j]);
        float2 v = __ldg((const float2*)(feat + (size_t)s * D_IN) + lane);
        acc.x += v.x; acc.y += v.y;
    }
    float rcp = 1.0f / fmaxf((float)deg, 1.0f);
    acc.x *= rcp; acc.y *= rcp;
    __nv_bfloat16 h0, l0, h1, l1; split2(acc.x, h0, l0); split2(acc.y, h1, l1);
    size_t idx = (size_t)warp * D_IN + lane * 2;
    *(unsigned*)&g_a1hi[idx] = pack_bf2(h0, h1);
    *(unsigned*)&g_a1lo[idx] = pack_bf2(l0, l1);
}

__global__ void gather2_kernel() {
    int warp = (blockIdx.x * blockDim.x + threadIdx.x) >> 5;
    int lane = threadIdx.x & 31;
    if (warp >= N_NODES) return;
    int deg = g_cnt_i[warp], start = g_rs[warp];
    float4 acc = make_float4(0.f, 0.f, 0.f, 0.f);
    for (int j = 0; j < deg; j++) {
        int s = __ldg(&g_adj[start + j]);
        size_t off = (size_t)s * D_H + lane * 4;
        uint2 vh = *(const uint2*)(g_h1hi + off);
        uint2 vl = *(const uint2*)(g_h1lo + off);
        float2 a = bf2f2(vh.x), b = bf2f2(vh.y), c = bf2f2(vl.x), d = bf2f2(vl.y);
        acc.x += a.x + c.x; acc.y += a.y + c.y;
        acc.z += b.x + d.x; acc.w += b.y + d.y;
    }
    float rcp = 1.0f / fmaxf((float)deg, 1.0f);
    acc.x *= rcp; acc.y *= rcp; acc.z *= rcp; acc.w *= rcp;
    __nv_bfloat16 h0,l0,h1,l1,h2,l2,h3,l3;
    split2(acc.x,h0,l0); split2(acc.y,h1,l1); split2(acc.z,h2,l2); split2(acc.w,h3,l3);
    size_t idx = (size_t)warp * D_H + lane * 4;
    *(uint2*)&g_a2hi[idx] = make_uint2(pack_bf2(h0,h1), pack_bf2(h2,h3));
    *(uint2*)&g_a2lo[idx] = make_uint2(pack_bf2(l0,l1), pack_bf2(l2,l3));
}

// ============================================================================
// Layer-1: h1 = sigmoid([feat | a1] @ W1 + b1)   (M=128/blk, N=128, K=128)
// ============================================================================
#define KP128 136
#define L1_SMEM ((4 * 128 * KP128) * 2)
__global__ void __launch_bounds__(256, 1)
l1_mma_kernel(const float* __restrict__ feat,
              const float* __restrict__ W1, const float* __restrict__ b1) {
    extern __shared__ unsigned char smraw[];
    __nv_bfloat16* Ahi = (__nv_bfloat16*)smraw;
    __nv_bfloat16* Alo = Ahi + 128 * KP128;
    __nv_bfloat16* Whi = Alo + 128 * KP128;
    __nv_bfloat16* Wlo = Whi + 128 * KP128;
    int tid = threadIdx.x;
    int node0 = blockIdx.x * 128;

    for (int i = tid; i < 128 * 128; i += 256) {   // W1: [128][128] -> Wt[n][k]
        int k = i >> 7, n = i & 127;
        __nv_bfloat16 h, l; split2(__ldg(&W1[i]), h, l);
        Whi[n * KP128 + k] = h; Wlo[n * KP128 + k] = l;
    }
    for (int i = tid; i < 128 * 64; i += 256) {    // A cols 0..63 = feat (split)
        int r = i >> 6, c = i & 63;
        int gn = node0 + r;
        float x = (gn < N_NODES) ? __ldg(&feat[(size_t)gn * D_IN + c]) : 0.f;
        __nv_bfloat16 h, l; split2(x, h, l);
        Ahi[r * KP128 + c] = h; Alo[r * KP128 + c] = l;
    }
    for (int i = tid; i < 128 * 32; i += 256) {    // A cols 64..127 = a1 (copy)
        int r = i >> 5, c2 = (i & 31) * 2;
        int gn = node0 + r;
        unsigned vh = 0, vl = 0;
        if (gn < N_NODES) {
            vh = *(const unsigned*)&g_a1hi[(size_t)gn * D_IN + c2];
            vl = *(const unsigned*)&g_a1lo[(size_t)gn * D_IN + c2];
        }
        *(unsigned*)&Ahi[r * KP128 + 64 + c2] = vh;
        *(unsigned*)&Alo[r * KP128 + 64 + c2] = vl;
    }
    __syncthreads();

    int w = tid >> 5, lane = tid & 31, g = lane >> 2, t = lane & 3;
    int m0 = (w & 3) * 32, n0 = (w >> 2) * 64;
    float acc[2][8][4];
#pragma unroll
    for (int a = 0; a < 2; a++)
#pragma unroll
        for (int b = 0; b < 8; b++)
#pragma unroll
            for (int c = 0; c < 4; c++) acc[a][b][c] = 0.f;

#pragma unroll
    for (int ks = 0; ks < 8; ks++)
        mma_step<8>(acc, Ahi, Alo, KP128, Whi, Wlo, KP128,
                    m0, n0, ks * 16, ks * 16, g, t);

#pragma unroll
    for (int mf = 0; mf < 2; mf++) {
        int r0 = node0 + m0 + mf * 16 + g;
#pragma unroll
        for (int nf = 0; nf < 8; nf++) {
            int col = n0 + nf * 8 + t * 2;
            float2 bv = *(const float2*)&b1[col];
            if (r0 < N_NODES) {
                float v0 = sigmoidf_(acc[mf][nf][0] + bv.x);
                float v1 = sigmoidf_(acc[mf][nf][1] + bv.y);
                __nv_bfloat16 h0, l0, h1, l1; split2(v0, h0, l0); split2(v1, h1, l1);
                size_t idx = (size_t)r0 * D_H + col;
                *(unsigned*)&g_h1hi[idx] = pack_bf2(h0, h1);
                *(unsigned*)&g_h1lo[idx] = pack_bf2(l0, l1);
            }
            if (r0 + 8 < N_NODES) {
                float v0 = sigmoidf_(acc[mf][nf][2] + bv.x);
                float v1 = sigmoidf_(acc[mf][nf][3] + bv.y);
                __nv_bfloat16 h0, l0, h1, l1; split2(v0, h0, l0); split2(v1, h1, l1);
                size_t idx = (size_t)(r0 + 8) * D_H + col;
                *(unsigned*)&g_h1hi[idx] = pack_bf2(h0, h1);
                *(unsigned*)&g_h1lo[idx] = pack_bf2(l0, l1);
            }
        }
    }
}

// ============================================================================
// Layer-2: h2 = sigmoid([h1 | a2] @ W2 + b2)   (M=128/blk, N=128, K=256)
// ============================================================================
#define KP256 264
#define L2_SMEM ((2 * 128 * KP128 + 2 * 128 * KP256) * 2)
__global__ void __launch_bounds__(256, 1)
l2_mma_kernel(const float* __restrict__ W2, const float* __restrict__ b2) {
    extern __shared__ unsigned char smraw[];
    __nv_bfloat16* Ahi = (__nv_bfloat16*)smraw;            // [128][KP128] (k-chunk)
    __nv_bfloat16* Alo = Ahi + 128 * KP128;
    __nv_bfloat16* Whi = Alo + 128 * KP128;                // [128][KP256] full K
    __nv_bfloat16* Wlo = Whi + 128 * KP256;
    int tid = threadIdx.x;
    int node0 = blockIdx.x * 128;

    for (int i = tid; i < 256 * 128; i += 256) {    // W2: [256][128] -> Wt[n][k]
        int k = i >> 7, n = i & 127;
        __nv_bfloat16 h, l; split2(__ldg(&W2[i]), h, l);
        Whi[n * KP256 + k] = h; Wlo[n * KP256 + k] = l;
    }
    for (int i = tid; i < 128 * 64; i += 256) {     // A chunk0 = h1 (copy)
        int r = i >> 6, c2 = (i & 63) * 2;
        int gn = node0 + r;
        unsigned vh = 0, vl = 0;
        if (gn < N_NODES) {
            vh = *(const unsigned*)&g_h1hi[(size_t)gn * D_H + c2];
            vl = *(const unsigned*)&g_h1lo[(size_t)gn * D_H + c2];
        }
        *(unsigned*)&Ahi[r * KP128 + c2] = vh;
        *(unsigned*)&Alo[r * KP128 + c2] = vl;
    }
    __syncthreads();

    int w = tid >> 5, lane = tid & 31, g = lane >> 2, t = lane & 3;
    int m0 = (w & 3) * 32, n0 = (w >> 2) * 64;
    float acc[2][8][4];
#pragma unroll
    for (int a = 0; a < 2; a++)
#pragma unroll
        for (int b = 0; b < 8; b++)
#pragma unroll
            for (int c = 0; c < 4; c++) acc[a][b][c] = 0.f;

#pragma unroll
    for (int ks = 0; ks < 8; ks++)
        mma_step<8>(acc, Ahi, Alo, KP128, Whi, Wlo, KP256,
                    m0, n0, ks * 16, ks * 16, g, t);
    __syncthreads();

    for (int i = tid; i < 128 * 64; i += 256) {     // A chunk1 = a2 (copy)
        int r = i >> 6, c2 = (i & 63) * 2;
        int gn = node0 + r;
        unsigned vh = 0, vl = 0;
        if (gn < N_NODES) {
            vh = *(const unsigned*)&g_a2hi[(size_t)gn * D_H + c2];
            vl = *(const unsigned*)&g_a2lo[(size_t)gn * D_H + c2];
        }
        *(unsigned*)&Ahi[r * KP128 + c2] = vh;
        *(unsigned*)&Alo[r * KP128 + c2] = vl;
    }
    __syncthreads();

#pragma unroll
    for (int ks = 0; ks < 8; ks++)
        mma_step<8>(acc, Ahi, Alo, KP128, Whi, Wlo, KP256,
                    m0, n0, ks * 16, 128 + ks * 16, g, t);

#pragma unroll
    for (int mf = 0; mf < 2; mf++) {
        int r0 = node0 + m0 + mf * 16 + g;
#pragma unroll
        for (int nf = 0; nf < 8; nf++) {
            int col = n0 + nf * 8 + t * 2;
            float2 bv = *(const float2*)&b2[col];
            if (r0 < N_NODES) {
                float v0 = sigmoidf_(acc[mf][nf][0] + bv.x);
                float v1 = sigmoidf_(acc[mf][nf][1] + bv.y);
                __nv_bfloat16 h0, l0, h1, l1; split2(v0, h0, l0); split2(v1, h1, l1);
                size_t idx = (size_t)r0 * D_H + col;
                *(unsigned*)&g_h2hi[idx] = pack_bf2(h0, h1);
                *(unsigned*)&g_h2lo[idx] = pack_bf2(l0, l1);
            }
            if (r0 + 8 < N_NODES) {
                float v0 = sigmoidf_(acc[mf][nf][2] + bv.x);
                float v1 = sigmoidf_(acc[mf][nf][3] + bv.y);
                __nv_bfloat16 h0, l0, h1, l1; split2(v0, h0, l0); split2(v1, h1, l1);
                size_t idx = (size_t)(r0 + 8) * D_H + col;
                *(unsigned*)&g_h2hi[idx] = pack_bf2(h0, h1);
                *(unsigned*)&g_h2lo[idx] = pack_bf2(l0, l1);
            }
        }
    }
}

// ============================================================================
// MLP-1: h3 = relu(h2 @ Wm1 + bm1)   (M=128/blk, N=256 in two 128-halves, K=128)
// ============================================================================
#define M1_SMEM ((4 * 128 * KP128) * 2)
__global__ void __launch_bounds__(256, 1)
m1_mma_kernel(const float* __restrict__ Wm1, const float* __restrict__ bm1) {
    extern __shared__ unsigned char smraw[];
    __nv_bfloat16* Ahi = (__nv_bfloat16*)smraw;
    __nv_bfloat16* Alo = Ahi + 128 * KP128;
    __nv_bfloat16* Whi = Alo + 128 * KP128;   // [128 n][KP128] per n-half
    __nv_bfloat16* Wlo = Whi + 128 * KP128;
    int tid = threadIdx.x;
    int node0 = blockIdx.x * 128;

    for (int i = tid; i < 128 * 64; i += 256) {     // A = h2 (copy)
        int r = i >> 6, c2 = (i & 63) * 2;
        int gn = node0 + r;
        unsigned vh = 0, vl = 0;
        if (gn < N_NODES) {
            vh = *(const unsigned*)&g_h2hi[(size_t)gn * D_H + c2];
            vl = *(const unsigned*)&g_h2lo[(size_t)gn * D_H + c2];
        }
        *(unsigned*)&Ahi[r * KP128 + c2] = vh;
        *(unsigned*)&Alo[r * KP128 + c2] = vl;
    }

    int w = tid >> 5, lane = tid & 31, g = lane >> 2, t = lane & 3;
    int m0 = (w & 3) * 32, n0 = (w >> 2) * 64;

    for (int nb = 0; nb < 2; nb++) {
        if (nb) __syncthreads();
        for (int i = tid; i < 128 * 128; i += 256) {  // W half: cols nb*128..+128
            int k = i >> 7, n = i & 127;
            __nv_bfloat16 h, l; split2(__ldg(&Wm1[k * 256 + nb * 128 + n]), h, l);
            Whi[n * KP128 + k] = h; Wlo[n * KP128 + k] = l;
        }
        __syncthreads();

        float acc[2][8][4];
#pragma unroll
        for (int a = 0; a < 2; a++)
#pragma unroll
            for (int b = 0; b < 8; b++)
#pragma unroll
                for (int c = 0; c < 4; c++) acc[a][b][c] = 0.f;

#pragma unroll
        for (int ks = 0; ks < 8; ks++)
            mma_step<8>(acc, Ahi, Alo, KP128, Whi, Wlo, KP128,
                        m0, n0, ks * 16, ks * 16, g, t);

#pragma unroll
        for (int mf = 0; mf < 2; mf++) {
            int r0 = node0 + m0 + mf * 16 + g;
#pragma unroll
            for (int nf = 0; nf < 8; nf++) {
                int col = nb * 128 + n0 + nf * 8 + t * 2;
                float2 bv = *(const float2*)&bm1[col];
                if (r0 < N_NODES) {
                    float v0 = fmaxf(acc[mf][nf][0] + bv.x, 0.f);
                    float v1 = fmaxf(acc[mf][nf][1] + bv.y, 0.f);
                    __nv_bfloat16 h0, l0, h1, l1; split2(v0, h0, l0); split2(v1, h1, l1);
                    size_t idx = (size_t)r0 * D_M + col;
                    *(unsigned*)&g_h3hi[idx] = pack_bf2(h0, h1);
                    *(unsigned*)&g_h3lo[idx] = pack_bf2(l0, l1);
                }
                if (r0 + 8 < N_NODES) {
                    float v0 = fmaxf(acc[mf][nf][2] + bv.x, 0.f);
                    float v1 = fmaxf(acc[mf][nf][3] + bv.y, 0.f);
                    __nv_bfloat16 h0, l0, h1, l1; split2(v0, h0, l0); split2(v1, h1, l1);
                    size_t idx = (size_t)(r0 + 8) * D_M + col;
                    *(unsigned*)&g_h3hi[idx] = pack_bf2(h0, h1);
                    *(unsigned*)&g_h3lo[idx] = pack_bf2(l0, l1);
                }
            }
        }
    }
}

// ============================================================================
// MLP-2: out = h3 @ Wm2 + bm2   (M=256/blk, N=40, K=256 in two 128-chunks)
// ============================================================================
#define M2_SMEM ((2 * 256 * KP128 + 2 * 40 * KP256) * 2)
__global__ void __launch_bounds__(256, 1)
m2_mma_kernel(const float* __restrict__ Wm2, const float* __restrict__ bm2,
              float* __restrict__ out) {
    extern __shared__ unsigned char smraw[];
    __nv_bfloat16* Ahi = (__nv_bfloat16*)smraw;            // [256][KP128]
    __nv_bfloat16* Alo = Ahi + 256 * KP128;
    __nv_bfloat16* Whi = Alo + 256 * KP128;                // [40][KP256]
    __nv_bfloat16* Wlo = Whi + 40 * KP256;
    int tid = threadIdx.x;
    int node0 = blockIdx.x * 256;

    for (int i = tid; i < 256 * 40; i += 256) {     // Wm2: [256][40] -> Wt[n][k]
        int k = i / 40, n = i % 40;
        __nv_bfloat16 h, l; split2(__ldg(&Wm2[i]), h, l);
        Whi[n * KP256 + k] = h; Wlo[n * KP256 + k] = l;
    }

    int w = tid >> 5, lane = tid & 31, g = lane >> 2, t = lane & 3;
    int m0 = w * 32, n0 = 0;
    float acc[2][5][4];
#pragma unroll
    for (int a = 0; a < 2; a++)
#pragma unroll
        for (int b = 0; b < 5; b++)
#pragma unroll
            for (int c = 0; c < 4; c++) acc[a][b][c] = 0.f;

    for (int kc = 0; kc < 2; kc++) {
        if (kc) __syncthreads();
        for (int i = tid; i < 256 * 64; i += 256) {  // A chunk = h3 (copy)
            int r = i >> 6, c2 = (i & 63) * 2;
            int gn = node0 + r;
            unsigned vh = 0, vl = 0;
            if (gn < N_NODES) {
                vh = *(const unsigned*)&g_h3hi[(size_t)gn * D_M + kc * 128 + c2];
                vl = *(const unsigned*)&g_h3lo[(size_t)gn * D_M + kc * 128 + c2];
            }
            *(unsigned*)&Ahi[r * KP128 + c2] = vh;
            *(unsigned*)&Alo[r * KP128 + c2] = vl;
        }
        __syncthreads();
#pragma unroll
        for (int ks = 0; ks < 8; ks++)
            mma_step<5>(acc, Ahi, Alo, KP128, Whi, Wlo, KP256,
                        m0, n0, ks * 16, kc * 128 + ks * 16, g, t);
    }

#pragma unroll
    for (int mf = 0; mf < 2; mf++) {
        int r0 = node0 + m0 + mf * 16 + g;
#pragma unroll
        for (int nf = 0; nf < 5; nf++) {
            int col = nf * 8 + t * 2;
            float2 bv = *(const float2*)&bm2[col];
            if (r0 < N_NODES) {
                float2 o = make_float2(acc[mf][nf][0] + bv.x, acc[mf][nf][1] + bv.y);
                *(float2*)&out[(size_t)r0 * D_OUT + col] = o;
            }
            if (r0 + 8 < N_NODES) {
                float2 o = make_float2(acc[mf][nf][2] + bv.x, acc[mf][nf][3] + bv.y);
                *(float2*)&out[(size_t)(r0 + 8) * D_OUT + col] = o;
            }
        }
    }
}

// ---------------- launch -----------------------------------------------------
extern "C" void kernel_launch(void* const* d_in, const int* in_sizes, int n_in,
                              void* d_out, int out_size) {
    const float* feat = (const float*)d_in[0];
    const int*   ei   = (const int*)d_in[1];     // int32 (JAX x64 disabled)
    const float* W1   = (const float*)d_in[2];
    const float* b1   = (const float*)d_in[3];
    const float* W2   = (const float*)d_in[4];
    const float* b2   = (const float*)d_in[5];
    const float* Wm1  = (const float*)d_in[6];
    const float* bm1  = (const float*)d_in[7];
    const float* Wm2  = (const float*)d_in[8];
    const float* bm2  = (const float*)d_in[9];
    float* out = (float*)d_out;

    cudaFuncSetAttribute(l1_mma_kernel, cudaFuncAttributeMaxDynamicSharedMemorySize, L1_SMEM);
    cudaFuncSetAttribute(l2_mma_kernel, cudaFuncAttributeMaxDynamicSharedMemorySize, L2_SMEM);
    cudaFuncSetAttribute(m1_mma_kernel, cudaFuncAttributeMaxDynamicSharedMemorySize, M1_SMEM);
    cudaFuncSetAttribute(m2_mma_kernel, cudaFuncAttributeMaxDynamicSharedMemorySize, M2_SMEM);

    // CSR build (shared by both layers)
    zero_cnt_kernel<<<(N_NODES + 255) / 256, 256>>>();
    hist_kernel<<<(N_EDGES + 255) / 256, 256>>>(ei);
    scan1_kernel<<<NB_SCAN, 256>>>();
    scan2_kernel<<<1, 512>>>();
    scan3_kernel<<<NB_SCAN, 256>>>();
    fill_kernel<<<(N_EDGES + 255) / 256, 256>>>(ei);

    // layer 1
    gather1_kernel<<<(N_NODES * 32 + 255) / 256, 256>>>(feat);
    l1_mma_kernel<<<(N_NODES + 127) / 128, 256, L1_SMEM>>>(feat, W1, b1);

    // layer 2
    gather2_kernel<<<(N_NODES * 32 + 255) / 256, 256>>>();
    l2_mma_kernel<<<(N_NODES + 127) / 128, 256, L2_SMEM>>>(W2, b2);

    // MLP
    m1_mma_kernel<<<(N_NODES + 127) / 128, 256, M1_SMEM>>>(Wm1, bm1);
    m2_mma_kernel<<<(N_NODES + 255) / 256, 256, M2_SMEM>>>(Wm2, bm2, out);
}

// round 8
// speedup vs baseline: 2.1738x; 1.5273x over previous
#include <cuda_runtime.h>
#include <cuda_bf16.h>

#define N_NODES 100000
#define N_EDGES 1600000
#define D_IN    64
#define D_H     128
#define D_M     256
#define D_OUT   40
#define NB_SCAN 391   // ceil(N_NODES/256)
#define KP128 136
#define KP256 264

// ---------------- device-global scratch --------------------------------------
__device__ int g_cnt_i[N_NODES];
__device__ int g_rs  [N_NODES];
__device__ int g_wr  [N_NODES];
__device__ int g_bsum[512];
__device__ int g_adj [N_EDGES];
__device__ __align__(16) __nv_bfloat16 g_fhi [(size_t)N_NODES * D_IN];
__device__ __align__(16) __nv_bfloat16 g_flo [(size_t)N_NODES * D_IN];
__device__ __align__(16) __nv_bfloat16 g_a1hi[(size_t)N_NODES * D_IN];
__device__ __align__(16) __nv_bfloat16 g_a1lo[(size_t)N_NODES * D_IN];
__device__ __align__(16) __nv_bfloat16 g_a2hi[(size_t)N_NODES * D_H];
__device__ __align__(16) __nv_bfloat16 g_a2lo[(size_t)N_NODES * D_H];
__device__ __align__(16) __nv_bfloat16 g_h1hi[(size_t)N_NODES * D_H];
__device__ __align__(16) __nv_bfloat16 g_h1lo[(size_t)N_NODES * D_H];
__device__ __align__(16) __nv_bfloat16 g_h2hi[(size_t)N_NODES * D_H];
__device__ __align__(16) __nv_bfloat16 g_h2lo[(size_t)N_NODES * D_H];
__device__ __align__(16) __nv_bfloat16 g_h3hi[(size_t)N_NODES * D_M];
__device__ __align__(16) __nv_bfloat16 g_h3lo[(size_t)N_NODES * D_M];
// pre-split weights, padded to smem tile layout (n-major, stride KP*)
__device__ __align__(16) __nv_bfloat16 g_w1hi[128 * KP128], g_w1lo[128 * KP128];
__device__ __align__(16) __nv_bfloat16 g_w2hi[128 * KP256], g_w2lo[128 * KP256];
__device__ __align__(16) __nv_bfloat16 g_m1hi[256 * KP128], g_m1lo[256 * KP128];
__device__ __align__(16) __nv_bfloat16 g_m2hi[ 40 * KP256], g_m2lo[ 40 * KP256];

// ---------------- helpers ----------------------------------------------------
__device__ __forceinline__ float sigmoidf_(float x) {
    return 1.0f / (1.0f + __expf(-x));
}
__device__ __forceinline__ void split2(float x, __nv_bfloat16& hi, __nv_bfloat16& lo) {
    hi = __float2bfloat16(x);
    lo = __float2bfloat16(x - __bfloat162float(hi));
}
__device__ __forceinline__ unsigned pack_bf2(__nv_bfloat16 a, __nv_bfloat16 b) {
    return (unsigned)__bfloat16_as_ushort(a) | ((unsigned)__bfloat16_as_ushort(b) << 16);
}
__device__ __forceinline__ float2 bf2f2(unsigned u) {
    __nv_bfloat162 b = *(__nv_bfloat162*)&u;
    return __bfloat1622float2(b);
}

__device__ __forceinline__ void mma_bf16(float c[4], const unsigned a[4],
                                         unsigned b0, unsigned b1) {
    asm volatile("mma.sync.aligned.m16n8k16.row.col.f32.bf16.bf16.f32 "
                 "{%0,%1,%2,%3}, {%4,%5,%6,%7}, {%8,%9}, {%0,%1,%2,%3};"
                 : "+f"(c[0]), "+f"(c[1]), "+f"(c[2]), "+f"(c[3])
                 : "r"(a[0]), "r"(a[1]), "r"(a[2]), "r"(a[3]), "r"(b0), "r"(b1));
}

// one k16 step of a (MF*16)x(NF*8) warp tile with hi/lo compensation
template<int MF, int NF>
__device__ __forceinline__ void mma_step(
    float (&acc)[MF][NF][4],
    const __nv_bfloat16* __restrict__ Ahi, const __nv_bfloat16* __restrict__ Alo, int KPa,
    const __nv_bfloat16* __restrict__ Whi, const __nv_bfloat16* __restrict__ Wlo, int KPw,
    int m0, int n0, int kbA, int kbW, int g, int t)
{
    unsigned ah[MF][4], al[MF][4];
#pragma unroll
    for (int mf = 0; mf < MF; mf++) {
        int r = m0 + mf * 16 + g;
        ah[mf][0] = *(const unsigned*)&Ahi[(r    ) * KPa + kbA     + t * 2];
        ah[mf][1] = *(const unsigned*)&Ahi[(r + 8) * KPa + kbA     + t * 2];
        ah[mf][2] = *(const unsigned*)&Ahi[(r    ) * KPa + kbA + 8 + t * 2];
        ah[mf][3] = *(const unsigned*)&Ahi[(r + 8) * KPa + kbA + 8 + t * 2];
        al[mf][0] = *(const unsigned*)&Alo[(r    ) * KPa + kbA     + t * 2];
        al[mf][1] = *(const unsigned*)&Alo[(r + 8) * KPa + kbA     + t * 2];
        al[mf][2] = *(const unsigned*)&Alo[(r    ) * KPa + kbA + 8 + t * 2];
        al[mf][3] = *(const unsigned*)&Alo[(r + 8) * KPa + kbA + 8 + t * 2];
    }
#pragma unroll
    for (int nf = 0; nf < NF; nf++) {
        int n = n0 + nf * 8 + g;
        unsigned bh0 = *(const unsigned*)&Whi[n * KPw + kbW     + t * 2];
        unsigned bh1 = *(const unsigned*)&Whi[n * KPw + kbW + 8 + t * 2];
        unsigned bl0 = *(const unsigned*)&Wlo[n * KPw + kbW     + t * 2];
        unsigned bl1 = *(const unsigned*)&Wlo[n * KPw + kbW + 8 + t * 2];
#pragma unroll
        for (int mf = 0; mf < MF; mf++) {
            mma_bf16(acc[mf][nf], ah[mf], bh0, bh1);
            mma_bf16(acc[mf][nf], ah[mf], bl0, bl1);
            mma_bf16(acc[mf][nf], al[mf], bh0, bh1);
        }
    }
}

// ---------------- CSR build --------------------------------------------------
__global__ void zero_cnt_kernel() {
    unsigned i = blockIdx.x * blockDim.x + threadIdx.x;
    if (i < N_NODES) g_cnt_i[i] = 0;
}
__global__ void hist_kernel(const int* __restrict__ ei) {
    unsigned e = blockIdx.x * blockDim.x + threadIdx.x;
    if (e >= N_EDGES) return;
    int s = __ldg(&ei[e]);
    int d = __ldg(&ei[N_EDGES + e]);
    if ((unsigned)s >= (unsigned)N_NODES || (unsigned)d >= (unsigned)N_NODES) return;
    atomicAdd(&g_cnt_i[d], 1);
}
__global__ void scan1_kernel() {
    __shared__ int sm[256];
    int t = threadIdx.x, b = blockIdx.x;
    int i = b * 256 + t;
    int v = (i < N_NODES) ? g_cnt_i[i] : 0;
    sm[t] = v; __syncthreads();
    for (int off = 1; off < 256; off <<= 1) {
        int x = (t >= off) ? sm[t - off] : 0;
        __syncthreads(); sm[t] += x; __syncthreads();
    }
    if (i < N_NODES) g_rs[i] = sm[t] - v;
    if (t == 255) g_bsum[b] = sm[255];
}
__global__ void scan2_kernel() {
    __shared__ int sm[512];
    int t = threadIdx.x;
    int v = (t < NB_SCAN) ? g_bsum[t] : 0;
    sm[t] = v; __syncthreads();
    for (int off = 1; off < 512; off <<= 1) {
        int x = (t >= off) ? sm[t - off] : 0;
        __syncthreads(); sm[t] += x; __syncthreads();
    }
    if (t < NB_SCAN) g_bsum[t] = sm[t] - v;
}
__global__ void scan3_kernel() {
    int i = blockIdx.x * blockDim.x + threadIdx.x;
    if (i >= N_NODES) return;
    int v = g_rs[i] + g_bsum[blockIdx.x];
    g_rs[i] = v;
    g_wr[i] = v;
}
__global__ void fill_kernel(const int* __restrict__ ei) {
    unsigned e = blockIdx.x * blockDim.x + threadIdx.x;
    if (e >= N_EDGES) return;
    int s = __ldg(&ei[e]);
    int d = __ldg(&ei[N_EDGES + e]);
    if ((unsigned)s >= (unsigned)N_NODES || (unsigned)d >= (unsigned)N_NODES) return;
    g_adj[atomicAdd(&g_wr[d], 1)] = s;
}

// ---------------- operand pre-split ------------------------------------------
__global__ void split_feat_kernel(const float* __restrict__ feat) {
    unsigned i = blockIdx.x * blockDim.x + threadIdx.x;
    if (i >= N_NODES * D_IN / 2) return;
    float2 v = __ldg(((const float2*)feat) + i);
    __nv_bfloat16 h0, l0, h1, l1;
    split2(v.x, h0, l0); split2(v.y, h1, l1);
    *(unsigned*)&g_fhi[i * 2] = pack_bf2(h0, h1);
    *(unsigned*)&g_flo[i * 2] = pack_bf2(l0, l1);
}
__global__ void split_w_kernel(const float* __restrict__ W1, const float* __restrict__ W2,
                               const float* __restrict__ Wm1, const float* __restrict__ Wm2) {
    int i = blockIdx.x * blockDim.x + threadIdx.x;
    __nv_bfloat16 h, l;
    if (i < 16384) {                        // W1 [128k][128n]
        int k = i >> 7, n = i & 127;
        split2(__ldg(&W1[i]), h, l);
        g_w1hi[n * KP128 + k] = h; g_w1lo[n * KP128 + k] = l;
    } else if (i < 49152) {                 // W2 [256k][128n]
        int j = i - 16384; int k = j >> 7, n = j & 127;
        split2(__ldg(&W2[j]), h, l);
        g_w2hi[n * KP256 + k] = h; g_w2lo[n * KP256 + k] = l;
    } else if (i < 81920) {                 // Wm1 [128k][256n]
        int j = i - 49152; int k = j >> 8, n = j & 255;
        split2(__ldg(&Wm1[j]), h, l);
        g_m1hi[n * KP128 + k] = h; g_m1lo[n * KP128 + k] = l;
    } else if (i < 92160) {                 // Wm2 [256k][40n]
        int j = i - 81920; int k = j / 40, n = j % 40;
        split2(__ldg(&Wm2[j]), h, l);
        g_m2hi[n * KP256 + k] = h; g_m2lo[n * KP256 + k] = l;
    }
}

// ---------------- gather-reduce (warp per node) ------------------------------
__global__ void gather1_kernel(const float* __restrict__ feat) {
    int warp = (blockIdx.x * blockDim.x + threadIdx.x) >> 5;
    int lane = threadIdx.x & 31;
    if (warp >= N_NODES) return;
    int deg = g_cnt_i[warp], start = g_rs[warp];
    float2 acc = make_float2(0.f, 0.f);
    for (int j = 0; j < deg; j++) {
        int s = __ldg(&g_adj[start + j]);
        float2 v = __ldg((const float2*)(feat + (size_t)s * D_IN) + lane);
        acc.x += v.x; acc.y += v.y;
    }
    float rcp = 1.0f / fmaxf((float)deg, 1.0f);
    acc.x *= rcp; acc.y *= rcp;
    __nv_bfloat16 h0, l0, h1, l1; split2(acc.x, h0, l0); split2(acc.y, h1, l1);
    size_t idx = (size_t)warp * D_IN + lane * 2;
    *(unsigned*)&g_a1hi[idx] = pack_bf2(h0, h1);
    *(unsigned*)&g_a1lo[idx] = pack_bf2(l0, l1);
}

__global__ void gather2_kernel() {
    int warp = (blockIdx.x * blockDim.x + threadIdx.x) >> 5;
    int lane = threadIdx.x & 31;
    if (warp >= N_NODES) return;
    int deg = g_cnt_i[warp], start = g_rs[warp];
    float4 acc = make_float4(0.f, 0.f, 0.f, 0.f);
    for (int j = 0; j < deg; j++) {
        int s = __ldg(&g_adj[start + j]);
        size_t off = (size_t)s * D_H + lane * 4;
        uint2 vh = *(const uint2*)(g_h1hi + off);
        uint2 vl = *(const uint2*)(g_h1lo + off);
        float2 a = bf2f2(vh.x), b = bf2f2(vh.y), c = bf2f2(vl.x), d = bf2f2(vl.y);
        acc.x += a.x + c.x; acc.y += a.y + c.y;
        acc.z += b.x + d.x; acc.w += b.y + d.y;
    }
    float rcp = 1.0f / fmaxf((float)deg, 1.0f);
    acc.x *= rcp; acc.y *= rcp; acc.z *= rcp; acc.w *= rcp;
    __nv_bfloat16 h0,l0,h1,l1,h2,l2,h3,l3;
    split2(acc.x,h0,l0); split2(acc.y,h1,l1); split2(acc.z,h2,l2); split2(acc.w,h3,l3);
    size_t idx = (size_t)warp * D_H + lane * 4;
    *(uint2*)&g_a2hi[idx] = make_uint2(pack_bf2(h0,h1), pack_bf2(h2,h3));
    *(uint2*)&g_a2lo[idx] = make_uint2(pack_bf2(l0,l1), pack_bf2(l2,l3));
}

// ============================================================================
// Layer-1: h1 = sigmoid([feat | a1] @ W1 + b1)  (M=64/blk, N=128, K=128, 2-occ)
// ============================================================================
#define L1_SMEM ((2 * 64 * KP128 + 2 * 128 * KP128) * 2)
__global__ void __launch_bounds__(256, 2)
l1_mma_kernel(const float* __restrict__ b1) {
    extern __shared__ unsigned char smraw[];
    __nv_bfloat16* Ahi = (__nv_bfloat16*)smraw;        // [64][KP128]
    __nv_bfloat16* Alo = Ahi + 64 * KP128;
    __nv_bfloat16* Whi = Alo + 64 * KP128;             // [128][KP128]
    __nv_bfloat16* Wlo = Whi + 128 * KP128;
    int tid = threadIdx.x;
    int node0 = blockIdx.x * 64;

    for (int i = tid; i < 128 * KP128 / 8; i += 256) {   // W blob copy (uint4)
        ((uint4*)Whi)[i] = ((const uint4*)g_w1hi)[i];
        ((uint4*)Wlo)[i] = ((const uint4*)g_w1lo)[i];
    }
    for (int i = tid; i < 64 * 8; i += 256) {            // A cols 0..63 = feat
        int r = i >> 3, q = i & 7;
        int gn = node0 + r;
        uint4 vh = make_uint4(0,0,0,0), vl = vh;
        if (gn < N_NODES) {
            vh = ((const uint4*)(g_fhi + (size_t)gn * D_IN))[q];
            vl = ((const uint4*)(g_flo + (size_t)gn * D_IN))[q];
        }
        *(uint4*)&Ahi[r * KP128 + q * 8] = vh;
        *(uint4*)&Alo[r * KP128 + q * 8] = vl;
    }
    for (int i = tid; i < 64 * 8; i += 256) {            // A cols 64..127 = a1
        int r = i >> 3, q = i & 7;
        int gn = node0 + r;
        uint4 vh = make_uint4(0,0,0,0), vl = vh;
        if (gn < N_NODES) {
            vh = ((const uint4*)(g_a1hi + (size_t)gn * D_IN))[q];
            vl = ((const uint4*)(g_a1lo + (size_t)gn * D_IN))[q];
        }
        *(uint4*)&Ahi[r * KP128 + 64 + q * 8] = vh;
        *(uint4*)&Alo[r * KP128 + 64 + q * 8] = vl;
    }
    __syncthreads();

    int w = tid >> 5, lane = tid & 31, g = lane >> 2, t = lane & 3;
    int m0 = (w & 3) * 16, n0 = (w >> 2) * 64;
    float acc[1][8][4];
#pragma unroll
    for (int b = 0; b < 8; b++)
#pragma unroll
        for (int c = 0; c < 4; c++) acc[0][b][c] = 0.f;

#pragma unroll
    for (int ks = 0; ks < 8; ks++)
        mma_step<1, 8>(acc, Ahi, Alo, KP128, Whi, Wlo, KP128,
                       m0, n0, ks * 16, ks * 16, g, t);

    int r0 = node0 + m0 + g;
#pragma unroll
    for (int nf = 0; nf < 8; nf++) {
        int col = n0 + nf * 8 + t * 2;
        float2 bv = *(const float2*)&b1[col];
        if (r0 < N_NODES) {
            float v0 = sigmoidf_(acc[0][nf][0] + bv.x);
            float v1 = sigmoidf_(acc[0][nf][1] + bv.y);
            __nv_bfloat16 h0, l0, h1, l1; split2(v0, h0, l0); split2(v1, h1, l1);
            size_t idx = (size_t)r0 * D_H + col;
            *(unsigned*)&g_h1hi[idx] = pack_bf2(h0, h1);
            *(unsigned*)&g_h1lo[idx] = pack_bf2(l0, l1);
        }
        if (r0 + 8 < N_NODES) {
            float v0 = sigmoidf_(acc[0][nf][2] + bv.x);
            float v1 = sigmoidf_(acc[0][nf][3] + bv.y);
            __nv_bfloat16 h0, l0, h1, l1; split2(v0, h0, l0); split2(v1, h1, l1);
            size_t idx = (size_t)(r0 + 8) * D_H + col;
            *(unsigned*)&g_h1hi[idx] = pack_bf2(h0, h1);
            *(unsigned*)&g_h1lo[idx] = pack_bf2(l0, l1);
        }
    }
}

// ============================================================================
// Layer-2: h2 = sigmoid([h1 | a2] @ W2 + b2)  (M=64/blk, N=128, K=256, 2-occ,
//          W re-staged per 128-k chunk)
// ============================================================================
#define L2_SMEM ((2 * 64 * KP128 + 2 * 128 * KP128) * 2)
__global__ void __launch_bounds__(256, 2)
l2_mma_kernel(const float* __restrict__ b2) {
    extern __shared__ unsigned char smraw[];
    __nv_bfloat16* Ahi = (__nv_bfloat16*)smraw;        // [64][KP128]
    __nv_bfloat16* Alo = Ahi + 64 * KP128;
    __nv_bfloat16* Whi = Alo + 64 * KP128;             // [128][KP128] per chunk
    __nv_bfloat16* Wlo = Whi + 128 * KP128;
    int tid = threadIdx.x;
    int node0 = blockIdx.x * 64;

    int w = tid >> 5, lane = tid & 31, g = lane >> 2, t = lane & 3;
    int m0 = (w & 3) * 16, n0 = (w >> 2) * 64;
    float acc[1][8][4];
#pragma unroll
    for (int b = 0; b < 8; b++)
#pragma unroll
        for (int c = 0; c < 4; c++) acc[0][b][c] = 0.f;

    for (int kc = 0; kc < 2; kc++) {
        if (kc) __syncthreads();
        for (int i = tid; i < 128 * 16; i += 256) {    // W chunk rows
            int n = i >> 4, q = i & 15;
            *(uint4*)&Whi[n * KP128 + q * 8] =
                *(const uint4*)&g_w2hi[n * KP256 + kc * 128 + q * 8];
            *(uint4*)&Wlo[n * KP128 + q * 8] =
                *(const uint4*)&g_w2lo[n * KP256 + kc * 128 + q * 8];
        }
        const __nv_bfloat16* srcHi = kc ? g_a2hi : g_h1hi;
        const __nv_bfloat16* srcLo = kc ? g_a2lo : g_h1lo;
        for (int i = tid; i < 64 * 16; i += 256) {     // A chunk = h1 / a2
            int r = i >> 4, q = i & 15;
            int gn = node0 + r;
            uint4 vh = make_uint4(0,0,0,0), vl = vh;
            if (gn < N_NODES) {
                vh = ((const uint4*)(srcHi + (size_t)gn * D_H))[q];
                vl = ((const uint4*)(srcLo + (size_t)gn * D_H))[q];
            }
            *(uint4*)&Ahi[r * KP128 + q * 8] = vh;
            *(uint4*)&Alo[r * KP128 + q * 8] = vl;
        }
        __syncthreads();
#pragma unroll
        for (int ks = 0; ks < 8; ks++)
            mma_step<1, 8>(acc, Ahi, Alo, KP128, Whi, Wlo, KP128,
                           m0, n0, ks * 16, ks * 16, g, t);
    }

    int r0 = node0 + m0 + g;
#pragma unroll
    for (int nf = 0; nf < 8; nf++) {
        int col = n0 + nf * 8 + t * 2;
        float2 bv = *(const float2*)&b2[col];
        if (r0 < N_NODES) {
            float v0 = sigmoidf_(acc[0][nf][0] + bv.x);
            float v1 = sigmoidf_(acc[0][nf][1] + bv.y);
            __nv_bfloat16 h0, l0, h1, l1; split2(v0, h0, l0); split2(v1, h1, l1);
            size_t idx = (size_t)r0 * D_H + col;
            *(unsigned*)&g_h2hi[idx] = pack_bf2(h0, h1);
            *(unsigned*)&g_h2lo[idx] = pack_bf2(l0, l1);
        }
        if (r0 + 8 < N_NODES) {
            float v0 = sigmoidf_(acc[0][nf][2] + bv.x);
            float v1 = sigmoidf_(acc[0][nf][3] + bv.y);
            __nv_bfloat16 h0, l0, h1, l1; split2(v0, h0, l0); split2(v1, h1, l1);
            size_t idx = (size_t)(r0 + 8) * D_H + col;
            *(unsigned*)&g_h2hi[idx] = pack_bf2(h0, h1);
            *(unsigned*)&g_h2lo[idx] = pack_bf2(l0, l1);
        }
    }
}

// ============================================================================
// MLP-1: h3 = relu(h2 @ Wm1 + bm1)  (M=64/blk, N=256 in two halves, K=128, 2-occ)
// ============================================================================
#define M1_SMEM ((2 * 64 * KP128 + 2 * 128 * KP128) * 2)
__global__ void __launch_bounds__(256, 2)
m1_mma_kernel(const float* __restrict__ bm1) {
    extern __shared__ unsigned char smraw[];
    __nv_bfloat16* Ahi = (__nv_bfloat16*)smraw;        // [64][KP128]
    __nv_bfloat16* Alo = Ahi + 64 * KP128;
    __nv_bfloat16* Whi = Alo + 64 * KP128;             // [128][KP128] per half
    __nv_bfloat16* Wlo = Whi + 128 * KP128;
    int tid = threadIdx.x;
    int node0 = blockIdx.x * 64;

    for (int i = tid; i < 64 * 16; i += 256) {           // A = h2 copy
        int r = i >> 4, q = i & 15;
        int gn = node0 + r;
        uint4 vh = make_uint4(0,0,0,0), vl = vh;
        if (gn < N_NODES) {
            vh = ((const uint4*)(g_h2hi + (size_t)gn * D_H))[q];
            vl = ((const uint4*)(g_h2lo + (size_t)gn * D_H))[q];
        }
        *(uint4*)&Ahi[r * KP128 + q * 8] = vh;
        *(uint4*)&Alo[r * KP128 + q * 8] = vl;
    }

    int w = tid >> 5, lane = tid & 31, g = lane >> 2, t = lane & 3;
    int m0 = (w & 3) * 16, n0 = (w >> 2) * 64;

    for (int nb = 0; nb < 2; nb++) {
        if (nb) __syncthreads();
        const uint4* srcH = (const uint4*)(g_m1hi + nb * 128 * KP128);
        const uint4* srcL = (const uint4*)(g_m1lo + nb * 128 * KP128);
        for (int i = tid; i < 128 * KP128 / 8; i += 256) {   // W half blob copy
            ((uint4*)Whi)[i] = srcH[i];
            ((uint4*)Wlo)[i] = srcL[i];
        }
        __syncthreads();

        float acc[1][8][4];
#pragma unroll
        for (int b = 0; b < 8; b++)
#pragma unroll
            for (int c = 0; c < 4; c++) acc[0][b][c] = 0.f;

#pragma unroll
        for (int ks = 0; ks < 8; ks++)
            mma_step<1, 8>(acc, Ahi, Alo, KP128, Whi, Wlo, KP128,
                           m0, n0, ks * 16, ks * 16, g, t);

        int r0 = node0 + m0 + g;
#pragma unroll
        for (int nf = 0; nf < 8; nf++) {
            int col = nb * 128 + n0 + nf * 8 + t * 2;
            float2 bv = *(const float2*)&bm1[col];
            if (r0 < N_NODES) {
                float v0 = fmaxf(acc[0][nf][0] + bv.x, 0.f);
                float v1 = fmaxf(acc[0][nf][1] + bv.y, 0.f);
                __nv_bfloat16 h0, l0, h1, l1; split2(v0, h0, l0); split2(v1, h1, l1);
                size_t idx = (size_t)r0 * D_M + col;
                *(unsigned*)&g_h3hi[idx] = pack_bf2(h0, h1);
                *(unsigned*)&g_h3lo[idx] = pack_bf2(l0, l1);
            }
            if (r0 + 8 < N_NODES) {
                float v0 = fmaxf(acc[0][nf][2] + bv.x, 0.f);
                float v1 = fmaxf(acc[0][nf][3] + bv.y, 0.f);
                __nv_bfloat16 h0, l0, h1, l1; split2(v0, h0, l0); split2(v1, h1, l1);
                size_t idx = (size_t)(r0 + 8) * D_M + col;
                *(unsigned*)&g_h3hi[idx] = pack_bf2(h0, h1);
                *(unsigned*)&g_h3lo[idx] = pack_bf2(l0, l1);
            }
        }
    }
}

// ============================================================================
// MLP-2: out = h3 @ Wm2 + bm2  (M=128/blk, N=40, K=256, W resident, A chunked,
//        2-occ)
// ============================================================================
#define M2_SMEM ((2 * 128 * KP128 + 2 * 40 * KP256) * 2)
__global__ void __launch_bounds__(256, 2)
m2_mma_kernel(const float* __restrict__ bm2, float* __restrict__ out) {
    extern __shared__ unsigned char smraw[];
    __nv_bfloat16* Ahi = (__nv_bfloat16*)smraw;        // [128][KP128] per chunk
    __nv_bfloat16* Alo = Ahi + 128 * KP128;
    __nv_bfloat16* Whi = Alo + 128 * KP128;            // [40][KP256] full K
    __nv_bfloat16* Wlo = Whi + 40 * KP256;
    int tid = threadIdx.x;
    int node0 = blockIdx.x * 128;

    for (int i = tid; i < 40 * KP256 / 8; i += 256) {    // W blob copy
        ((uint4*)Whi)[i] = ((const uint4*)g_m2hi)[i];
        ((uint4*)Wlo)[i] = ((const uint4*)g_m2lo)[i];
    }

    int w = tid >> 5, lane = tid & 31, g = lane >> 2, t = lane & 3;
    int m0 = w * 16, n0 = 0;
    float acc[1][5][4];
#pragma unroll
    for (int b = 0; b < 5; b++)
#pragma unroll
        for (int c = 0; c < 4; c++) acc[0][b][c] = 0.f;

    for (int kc = 0; kc < 2; kc++) {
        if (kc) __syncthreads();
        for (int i = tid; i < 128 * 16; i += 256) {      // A chunk = h3 copy
            int r = i >> 4, q = i & 15;
            int gn = node0 + r;
            uint4 vh = make_uint4(0,0,0,0), vl = vh;
            if (gn < N_NODES) {
                vh = ((const uint4*)(g_h3hi + (size_t)gn * D_M + kc * 128))[q];
                vl = ((const uint4*)(g_h3lo + (size_t)gn * D_M + kc * 128))[q];
            }
            *(uint4*)&Ahi[r * KP128 + q * 8] = vh;
            *(uint4*)&Alo[r * KP128 + q * 8] = vl;
        }
        __syncthreads();
#pragma unroll
        for (int ks = 0; ks < 8; ks++)
            mma_step<1, 5>(acc, Ahi, Alo, KP128, Whi, Wlo, KP256,
                           m0, n0, ks * 16, kc * 128 + ks * 16, g, t);
    }

    int r0 = node0 + m0 + g;
#pragma unroll
    for (int nf = 0; nf < 5; nf++) {
        int col = nf * 8 + t * 2;
        float2 bv = *(const float2*)&bm2[col];
        if (r0 < N_NODES) {
            float2 o = make_float2(acc[0][nf][0] + bv.x, acc[0][nf][1] + bv.y);
            *(float2*)&out[(size_t)r0 * D_OUT + col] = o;
        }
        if (r0 + 8 < N_NODES) {
            float2 o = make_float2(acc[0][nf][2] + bv.x, acc[0][nf][3] + bv.y);
            *(float2*)&out[(size_t)(r0 + 8) * D_OUT + col] = o;
        }
    }
}

// ---------------- launch -----------------------------------------------------
extern "C" void kernel_launch(void* const* d_in, const int* in_sizes, int n_in,
                              void* d_out, int out_size) {
    const float* feat = (const float*)d_in[0];
    const int*   ei   = (const int*)d_in[1];     // int32 (JAX x64 disabled)
    const float* W1   = (const float*)d_in[2];
    const float* b1   = (const float*)d_in[3];
    const float* W2   = (const float*)d_in[4];
    const float* b2   = (const float*)d_in[5];
    const float* Wm1  = (const float*)d_in[6];
    const float* bm1  = (const float*)d_in[7];
    const float* Wm2  = (const float*)d_in[8];
    const float* bm2  = (const float*)d_in[9];
    float* out = (float*)d_out;

    cudaFuncSetAttribute(l1_mma_kernel, cudaFuncAttributeMaxDynamicSharedMemorySize, L1_SMEM);
    cudaFuncSetAttribute(l2_mma_kernel, cudaFuncAttributeMaxDynamicSharedMemorySize, L2_SMEM);
    cudaFuncSetAttribute(m1_mma_kernel, cudaFuncAttributeMaxDynamicSharedMemorySize, M1_SMEM);
    cudaFuncSetAttribute(m2_mma_kernel, cudaFuncAttributeMaxDynamicSharedMemorySize, M2_SMEM);

    // CSR build
    zero_cnt_kernel<<<(N_NODES + 255) / 256, 256>>>();
    hist_kernel<<<(N_EDGES + 255) / 256, 256>>>(ei);
    scan1_kernel<<<NB_SCAN, 256>>>();
    scan2_kernel<<<1, 512>>>();
    scan3_kernel<<<NB_SCAN, 256>>>();
    fill_kernel<<<(N_EDGES + 255) / 256, 256>>>(ei);

    // pre-split static operands
    split_feat_kernel<<<(N_NODES * D_IN / 2 + 255) / 256, 256>>>(feat);
    split_w_kernel<<<(92160 + 255) / 256, 256>>>(W1, W2, Wm1, Wm2);

    // layer 1
    gather1_kernel<<<(N_NODES * 32 + 255) / 256, 256>>>(feat);
    l1_mma_kernel<<<(N_NODES + 63) / 64, 256, L1_SMEM>>>(b1);

    // layer 2
    gather2_kernel<<<(N_NODES * 32 + 255) / 256, 256>>>();
    l2_mma_kernel<<<(N_NODES + 63) / 64, 256, L2_SMEM>>>(b2);

    // MLP
    m1_mma_kernel<<<(N_NODES + 63) / 64, 256, M1_SMEM>>>(bm1);
    m2_mma_kernel<<<(N_NODES + 127) / 128, 256, M2_SMEM>>>(bm2, out);
}

// round 9
// speedup vs baseline: 2.5478x; 1.1720x over previous
#include <cuda_runtime.h>
#include <cuda_bf16.h>

#define N_NODES 100000
#define N_EDGES 1600000
#define D_IN    64
#define D_H     128
#define D_M     256
#define D_OUT   40
#define NB_SCAN 391   // ceil(N_NODES/256)
#define KP128 136
#define KP256 264

// ---------------- device-global scratch --------------------------------------
__device__ int g_cnt_i[N_NODES];
__device__ int g_rs  [N_NODES];
__device__ int g_wr  [N_NODES];
__device__ int g_bsum[512];
__device__ int g_adj [N_EDGES];
__device__ __align__(16) __nv_bfloat16 g_fhi [(size_t)N_NODES * D_IN];
__device__ __align__(16) __nv_bfloat16 g_flo [(size_t)N_NODES * D_IN];
__device__ __align__(16) __nv_bfloat16 g_a1hi[(size_t)N_NODES * D_IN];
__device__ __align__(16) __nv_bfloat16 g_a1lo[(size_t)N_NODES * D_IN];
__device__ __align__(16) __nv_bfloat16 g_a2hi[(size_t)N_NODES * D_H];
__device__ __align__(16) __nv_bfloat16 g_a2lo[(size_t)N_NODES * D_H];
__device__ __align__(16) __nv_bfloat16 g_h1hi[(size_t)N_NODES * D_H];
__device__ __align__(16) __nv_bfloat16 g_h1lo[(size_t)N_NODES * D_H];
// pre-split weights, padded to smem tile layout (n-major, stride KP*)
__device__ __align__(16) __nv_bfloat16 g_w1hi[128 * KP128], g_w1lo[128 * KP128];
__device__ __align__(16) __nv_bfloat16 g_w2hi[128 * KP256], g_w2lo[128 * KP256];
__device__ __align__(16) __nv_bfloat16 g_m1hi[256 * KP128], g_m1lo[256 * KP128];
__device__ __align__(16) __nv_bfloat16 g_m2hi[ 40 * KP256], g_m2lo[ 40 * KP256];

// ---------------- helpers ----------------------------------------------------
__device__ __forceinline__ float sigmoidf_(float x) {
    return 1.0f / (1.0f + __expf(-x));
}
__device__ __forceinline__ void split2(float x, __nv_bfloat16& hi, __nv_bfloat16& lo) {
    hi = __float2bfloat16(x);
    lo = __float2bfloat16(x - __bfloat162float(hi));
}
__device__ __forceinline__ unsigned pack_bf2(__nv_bfloat16 a, __nv_bfloat16 b) {
    return (unsigned)__bfloat16_as_ushort(a) | ((unsigned)__bfloat16_as_ushort(b) << 16);
}
__device__ __forceinline__ float2 bf2f2(unsigned u) {
    __nv_bfloat162 b = *(__nv_bfloat162*)&u;
    return __bfloat1622float2(b);
}

__device__ __forceinline__ void mma_bf16(float c[4], const unsigned a[4],
                                         unsigned b0, unsigned b1) {
    asm volatile("mma.sync.aligned.m16n8k16.row.col.f32.bf16.bf16.f32 "
                 "{%0,%1,%2,%3}, {%4,%5,%6,%7}, {%8,%9}, {%0,%1,%2,%3};"
                 : "+f"(c[0]), "+f"(c[1]), "+f"(c[2]), "+f"(c[3])
                 : "r"(a[0]), "r"(a[1]), "r"(a[2]), "r"(a[3]), "r"(b0), "r"(b1));
}

// one k16 step of a (MF*16)x(NF*8) warp tile with hi/lo compensation
template<int MF, int NF>
__device__ __forceinline__ void mma_step(
    float (&acc)[MF][NF][4],
    const __nv_bfloat16* __restrict__ Ahi, const __nv_bfloat16* __restrict__ Alo, int KPa,
    const __nv_bfloat16* __restrict__ Whi, const __nv_bfloat16* __restrict__ Wlo, int KPw,
    int m0, int n0, int kbA, int kbW, int g, int t)
{
    unsigned ah[MF][4], al[MF][4];
#pragma unroll
    for (int mf = 0; mf < MF; mf++) {
        int r = m0 + mf * 16 + g;
        ah[mf][0] = *(const unsigned*)&Ahi[(r    ) * KPa + kbA     + t * 2];
        ah[mf][1] = *(const unsigned*)&Ahi[(r + 8) * KPa + kbA     + t * 2];
        ah[mf][2] = *(const unsigned*)&Ahi[(r    ) * KPa + kbA + 8 + t * 2];
        ah[mf][3] = *(const unsigned*)&Ahi[(r + 8) * KPa + kbA + 8 + t * 2];
        al[mf][0] = *(const unsigned*)&Alo[(r    ) * KPa + kbA     + t * 2];
        al[mf][1] = *(const unsigned*)&Alo[(r + 8) * KPa + kbA     + t * 2];
        al[mf][2] = *(const unsigned*)&Alo[(r    ) * KPa + kbA + 8 + t * 2];
        al[mf][3] = *(const unsigned*)&Alo[(r + 8) * KPa + kbA + 8 + t * 2];
    }
#pragma unroll
    for (int nf = 0; nf < NF; nf++) {
        int n = n0 + nf * 8 + g;
        unsigned bh0 = *(const unsigned*)&Whi[n * KPw + kbW     + t * 2];
        unsigned bh1 = *(const unsigned*)&Whi[n * KPw + kbW + 8 + t * 2];
        unsigned bl0 = *(const unsigned*)&Wlo[n * KPw + kbW     + t * 2];
        unsigned bl1 = *(const unsigned*)&Wlo[n * KPw + kbW + 8 + t * 2];
#pragma unroll
        for (int mf = 0; mf < MF; mf++) {
            mma_bf16(acc[mf][nf], ah[mf], bh0, bh1);
            mma_bf16(acc[mf][nf], ah[mf], bl0, bl1);
            mma_bf16(acc[mf][nf], al[mf], bh0, bh1);
        }
    }
}

// ---------------- CSR build --------------------------------------------------
__global__ void zero_cnt_kernel() {
    unsigned i = blockIdx.x * blockDim.x + threadIdx.x;
    if (i < N_NODES) g_cnt_i[i] = 0;
}
__global__ void hist_kernel(const int* __restrict__ ei) {
    unsigned e = blockIdx.x * blockDim.x + threadIdx.x;
    if (e >= N_EDGES) return;
    int s = __ldg(&ei[e]);
    int d = __ldg(&ei[N_EDGES + e]);
    if ((unsigned)s >= (unsigned)N_NODES || (unsigned)d >= (unsigned)N_NODES) return;
    atomicAdd(&g_cnt_i[d], 1);
}
__global__ void scan1_kernel() {
    __shared__ int sm[256];
    int t = threadIdx.x, b = blockIdx.x;
    int i = b * 256 + t;
    int v = (i < N_NODES) ? g_cnt_i[i] : 0;
    sm[t] = v; __syncthreads();
    for (int off = 1; off < 256; off <<= 1) {
        int x = (t >= off) ? sm[t - off] : 0;
        __syncthreads(); sm[t] += x; __syncthreads();
    }
    if (i < N_NODES) g_rs[i] = sm[t] - v;
    if (t == 255) g_bsum[b] = sm[255];
}
__global__ void scan2_kernel() {
    __shared__ int sm[512];
    int t = threadIdx.x;
    int v = (t < NB_SCAN) ? g_bsum[t] : 0;
    sm[t] = v; __syncthreads();
    for (int off = 1; off < 512; off <<= 1) {
        int x = (t >= off) ? sm[t - off] : 0;
        __syncthreads(); sm[t] += x; __syncthreads();
    }
    if (t < NB_SCAN) g_bsum[t] = sm[t] - v;
}
__global__ void scan3_kernel() {
    int i = blockIdx.x * blockDim.x + threadIdx.x;
    if (i >= N_NODES) return;
    int v = g_rs[i] + g_bsum[blockIdx.x];
    g_rs[i] = v;
    g_wr[i] = v;
}
__global__ void fill_kernel(const int* __restrict__ ei) {
    unsigned e = blockIdx.x * blockDim.x + threadIdx.x;
    if (e >= N_EDGES) return;
    int s = __ldg(&ei[e]);
    int d = __ldg(&ei[N_EDGES + e]);
    if ((unsigned)s >= (unsigned)N_NODES || (unsigned)d >= (unsigned)N_NODES) return;
    g_adj[atomicAdd(&g_wr[d], 1)] = s;
}

// ---------------- operand pre-split ------------------------------------------
__global__ void split_feat_kernel(const float* __restrict__ feat) {
    unsigned i = blockIdx.x * blockDim.x + threadIdx.x;
    if (i >= N_NODES * D_IN / 2) return;
    float2 v = __ldg(((const float2*)feat) + i);
    __nv_bfloat16 h0, l0, h1, l1;
    split2(v.x, h0, l0); split2(v.y, h1, l1);
    *(unsigned*)&g_fhi[i * 2] = pack_bf2(h0, h1);
    *(unsigned*)&g_flo[i * 2] = pack_bf2(l0, l1);
}
__global__ void split_w_kernel(const float* __restrict__ W1, const float* __restrict__ W2,
                               const float* __restrict__ Wm1, const float* __restrict__ Wm2) {
    int i = blockIdx.x * blockDim.x + threadIdx.x;
    __nv_bfloat16 h, l;
    if (i < 16384) {                        // W1 [128k][128n]
        int k = i >> 7, n = i & 127;
        split2(__ldg(&W1[i]), h, l);
        g_w1hi[n * KP128 + k] = h; g_w1lo[n * KP128 + k] = l;
    } else if (i < 49152) {                 // W2 [256k][128n]
        int j = i - 16384; int k = j >> 7, n = j & 127;
        split2(__ldg(&W2[j]), h, l);
        g_w2hi[n * KP256 + k] = h; g_w2lo[n * KP256 + k] = l;
    } else if (i < 81920) {                 // Wm1 [128k][256n]
        int j = i - 49152; int k = j >> 8, n = j & 255;
        split2(__ldg(&Wm1[j]), h, l);
        g_m1hi[n * KP128 + k] = h; g_m1lo[n * KP128 + k] = l;
    } else if (i < 92160) {                 // Wm2 [256k][40n]
        int j = i - 81920; int k = j / 40, n = j % 40;
        split2(__ldg(&Wm2[j]), h, l);
        g_m2hi[n * KP256 + k] = h; g_m2lo[n * KP256 + k] = l;
    }
}

// ---------------- gather-reduce (warp per node) ------------------------------
__global__ void gather1_kernel(const float* __restrict__ feat) {
    int warp = (blockIdx.x * blockDim.x + threadIdx.x) >> 5;
    int lane = threadIdx.x & 31;
    if (warp >= N_NODES) return;
    int deg = g_cnt_i[warp], start = g_rs[warp];
    float2 acc = make_float2(0.f, 0.f);
    for (int j = 0; j < deg; j++) {
        int s = __ldg(&g_adj[start + j]);
        float2 v = __ldg((const float2*)(feat + (size_t)s * D_IN) + lane);
        acc.x += v.x; acc.y += v.y;
    }
    float rcp = 1.0f / fmaxf((float)deg, 1.0f);
    acc.x *= rcp; acc.y *= rcp;
    __nv_bfloat16 h0, l0, h1, l1; split2(acc.x, h0, l0); split2(acc.y, h1, l1);
    size_t idx = (size_t)warp * D_IN + lane * 2;
    *(unsigned*)&g_a1hi[idx] = pack_bf2(h0, h1);
    *(unsigned*)&g_a1lo[idx] = pack_bf2(l0, l1);
}

__global__ void gather2_kernel() {
    int warp = (blockIdx.x * blockDim.x + threadIdx.x) >> 5;
    int lane = threadIdx.x & 31;
    if (warp >= N_NODES) return;
    int deg = g_cnt_i[warp], start = g_rs[warp];
    float4 acc = make_float4(0.f, 0.f, 0.f, 0.f);
    for (int j = 0; j < deg; j++) {
        int s = __ldg(&g_adj[start + j]);
        size_t off = (size_t)s * D_H + lane * 4;
        uint2 vh = *(const uint2*)(g_h1hi + off);
        uint2 vl = *(const uint2*)(g_h1lo + off);
        float2 a = bf2f2(vh.x), b = bf2f2(vh.y), c = bf2f2(vl.x), d = bf2f2(vl.y);
        acc.x += a.x + c.x; acc.y += a.y + c.y;
        acc.z += b.x + d.x; acc.w += b.y + d.y;
    }
    float rcp = 1.0f / fmaxf((float)deg, 1.0f);
    acc.x *= rcp; acc.y *= rcp; acc.z *= rcp; acc.w *= rcp;
    __nv_bfloat16 h0,l0,h1,l1,h2,l2,h3,l3;
    split2(acc.x,h0,l0); split2(acc.y,h1,l1); split2(acc.z,h2,l2); split2(acc.w,h3,l3);
    size_t idx = (size_t)warp * D_H + lane * 4;
    *(uint2*)&g_a2hi[idx] = make_uint2(pack_bf2(h0,h1), pack_bf2(h2,h3));
    *(uint2*)&g_a2lo[idx] = make_uint2(pack_bf2(l0,l1), pack_bf2(l2,l3));
}

// ============================================================================
// Layer-1: h1 = sigmoid([feat | a1] @ W1 + b1)  (M=64/blk, N=128, K=128, 2-occ)
// ============================================================================
#define L1_SMEM ((2 * 64 * KP128 + 2 * 128 * KP128) * 2)
__global__ void __launch_bounds__(256, 2)
l1_mma_kernel(const float* __restrict__ b1) {
    extern __shared__ unsigned char smraw[];
    __nv_bfloat16* Ahi = (__nv_bfloat16*)smraw;        // [64][KP128]
    __nv_bfloat16* Alo = Ahi + 64 * KP128;
    __nv_bfloat16* Whi = Alo + 64 * KP128;             // [128][KP128]
    __nv_bfloat16* Wlo = Whi + 128 * KP128;
    int tid = threadIdx.x;
    int node0 = blockIdx.x * 64;

    for (int i = tid; i < 128 * KP128 / 8; i += 256) {   // W blob copy (uint4)
        ((uint4*)Whi)[i] = ((const uint4*)g_w1hi)[i];
        ((uint4*)Wlo)[i] = ((const uint4*)g_w1lo)[i];
    }
    for (int i = tid; i < 64 * 8; i += 256) {            // A cols 0..63 = feat
        int r = i >> 3, q = i & 7;
        int gn = node0 + r;
        uint4 vh = make_uint4(0,0,0,0), vl = vh;
        if (gn < N_NODES) {
            vh = ((const uint4*)(g_fhi + (size_t)gn * D_IN))[q];
            vl = ((const uint4*)(g_flo + (size_t)gn * D_IN))[q];
        }
        *(uint4*)&Ahi[r * KP128 + q * 8] = vh;
        *(uint4*)&Alo[r * KP128 + q * 8] = vl;
    }
    for (int i = tid; i < 64 * 8; i += 256) {            // A cols 64..127 = a1
        int r = i >> 3, q = i & 7;
        int gn = node0 + r;
        uint4 vh = make_uint4(0,0,0,0), vl = vh;
        if (gn < N_NODES) {
            vh = ((const uint4*)(g_a1hi + (size_t)gn * D_IN))[q];
            vl = ((const uint4*)(g_a1lo + (size_t)gn * D_IN))[q];
        }
        *(uint4*)&Ahi[r * KP128 + 64 + q * 8] = vh;
        *(uint4*)&Alo[r * KP128 + 64 + q * 8] = vl;
    }
    __syncthreads();

    int w = tid >> 5, lane = tid & 31, g = lane >> 2, t = lane & 3;
    int m0 = (w & 3) * 16, n0 = (w >> 2) * 64;
    float acc[1][8][4];
#pragma unroll
    for (int b = 0; b < 8; b++)
#pragma unroll
        for (int c = 0; c < 4; c++) acc[0][b][c] = 0.f;

#pragma unroll
    for (int ks = 0; ks < 8; ks++)
        mma_step<1, 8>(acc, Ahi, Alo, KP128, Whi, Wlo, KP128,
                       m0, n0, ks * 16, ks * 16, g, t);

    int r0 = node0 + m0 + g;
#pragma unroll
    for (int nf = 0; nf < 8; nf++) {
        int col = n0 + nf * 8 + t * 2;
        float2 bv = *(const float2*)&b1[col];
        if (r0 < N_NODES) {
            float v0 = sigmoidf_(acc[0][nf][0] + bv.x);
            float v1 = sigmoidf_(acc[0][nf][1] + bv.y);
            __nv_bfloat16 h0, l0, h1, l1; split2(v0, h0, l0); split2(v1, h1, l1);
            size_t idx = (size_t)r0 * D_H + col;
            *(unsigned*)&g_h1hi[idx] = pack_bf2(h0, h1);
            *(unsigned*)&g_h1lo[idx] = pack_bf2(l0, l1);
        }
        if (r0 + 8 < N_NODES) {
            float v0 = sigmoidf_(acc[0][nf][2] + bv.x);
            float v1 = sigmoidf_(acc[0][nf][3] + bv.y);
            __nv_bfloat16 h0, l0, h1, l1; split2(v0, h0, l0); split2(v1, h1, l1);
            size_t idx = (size_t)(r0 + 8) * D_H + col;
            *(unsigned*)&g_h1hi[idx] = pack_bf2(h0, h1);
            *(unsigned*)&g_h1lo[idx] = pack_bf2(l0, l1);
        }
    }
}

// ============================================================================
// Fused L2 + MLP1 + MLP2 (M=64/blk, 2-occ).  h2 and h3 never leave smem.
//   phase A: h2 = sigmoid([h1 | a2] @ W2 + b2)  -> A buffer
//   per n-half nb: h3half = relu(h2 @ Wm1[:,nb*128:+128] + bm1) -> W buffer
//                  acc2 += h3half @ Wm2[nb*128:+128, :]
//   out = acc2 + bm2
// ============================================================================
#define F_SMEM ((2 * 64 * KP128 + 2 * 128 * KP128) * 2)
__global__ void __launch_bounds__(256, 2)
fused_l2_mlp_kernel(const float* __restrict__ b2, const float* __restrict__ bm1,
                    const float* __restrict__ bm2, float* __restrict__ out) {
    extern __shared__ unsigned char smraw[];
    __nv_bfloat16* Ahi = (__nv_bfloat16*)smraw;        // [64][KP128]
    __nv_bfloat16* Alo = Ahi + 64 * KP128;
    __nv_bfloat16* Whi = Alo + 64 * KP128;             // [128][KP128]
    __nv_bfloat16* Wlo = Whi + 128 * KP128;
    int tid = threadIdx.x;
    int node0 = blockIdx.x * 64;
    int w = tid >> 5, lane = tid & 31, g = lane >> 2, t = lane & 3;
    int m0 = (w & 3) * 16, n0 = (w >> 2) * 64;

    // ---------------- phase A: layer-2 GEMM ----------------
    float acc[1][8][4];
#pragma unroll
    for (int b = 0; b < 8; b++)
#pragma unroll
        for (int c = 0; c < 4; c++) acc[0][b][c] = 0.f;

    for (int kc = 0; kc < 2; kc++) {
        if (kc) __syncthreads();
        for (int i = tid; i < 128 * 16; i += 256) {    // W2 chunk rows
            int n = i >> 4, q = i & 15;
            *(uint4*)&Whi[n * KP128 + q * 8] =
                *(const uint4*)&g_w2hi[n * KP256 + kc * 128 + q * 8];
            *(uint4*)&Wlo[n * KP128 + q * 8] =
                *(const uint4*)&g_w2lo[n * KP256 + kc * 128 + q * 8];
        }
        const __nv_bfloat16* srcHi = kc ? g_a2hi : g_h1hi;
        const __nv_bfloat16* srcLo = kc ? g_a2lo : g_h1lo;
        for (int i = tid; i < 64 * 16; i += 256) {     // A chunk = h1 / a2
            int r = i >> 4, q = i & 15;
            int gn = node0 + r;
            uint4 vh = make_uint4(0,0,0,0), vl = vh;
            if (gn < N_NODES) {
                vh = ((const uint4*)(srcHi + (size_t)gn * D_H))[q];
                vl = ((const uint4*)(srcLo + (size_t)gn * D_H))[q];
            }
            *(uint4*)&Ahi[r * KP128 + q * 8] = vh;
            *(uint4*)&Alo[r * KP128 + q * 8] = vl;
        }
        __syncthreads();
#pragma unroll
        for (int ks = 0; ks < 8; ks++)
            mma_step<1, 8>(acc, Ahi, Alo, KP128, Whi, Wlo, KP128,
                           m0, n0, ks * 16, ks * 16, g, t);
    }
    __syncthreads();     // all warps done reading A before overwriting with h2

    // epilogue A: h2 -> A buffer (sigmoid + split), rows are block-local
    {
        int rr = m0 + g;
#pragma unroll
        for (int nf = 0; nf < 8; nf++) {
            int col = n0 + nf * 8 + t * 2;
            float2 bv = *(const float2*)&b2[col];
            float v0 = sigmoidf_(acc[0][nf][0] + bv.x);
            float v1 = sigmoidf_(acc[0][nf][1] + bv.y);
            float v2 = sigmoidf_(acc[0][nf][2] + bv.x);
            float v3 = sigmoidf_(acc[0][nf][3] + bv.y);
            __nv_bfloat16 h0, l0, h1, l1; split2(v0, h0, l0); split2(v1, h1, l1);
            *(unsigned*)&Ahi[rr * KP128 + col] = pack_bf2(h0, h1);
            *(unsigned*)&Alo[rr * KP128 + col] = pack_bf2(l0, l1);
            split2(v2, h0, l0); split2(v3, h1, l1);
            *(unsigned*)&Ahi[(rr + 8) * KP128 + col] = pack_bf2(h0, h1);
            *(unsigned*)&Alo[(rr + 8) * KP128 + col] = pack_bf2(l0, l1);
        }
    }
    __syncthreads();

    // ---------------- phase B: MLP1 half + MLP2 partial, per nb -------------
    // m2 accumulators (warps 0-3, 16 rows each)
    float acc2[1][5][4];
#pragma unroll
    for (int b = 0; b < 5; b++)
#pragma unroll
        for (int c = 0; c < 4; c++) acc2[0][b][c] = 0.f;

    for (int nb = 0; nb < 2; nb++) {
        if (nb) __syncthreads();
        {   // stage Wm1 half nb (blob copy)
            const uint4* srcH = (const uint4*)(g_m1hi + nb * 128 * KP128);
            const uint4* srcL = (const uint4*)(g_m1lo + nb * 128 * KP128);
            for (int i = tid; i < 128 * KP128 / 8; i += 256) {
                ((uint4*)Whi)[i] = srcH[i];
                ((uint4*)Wlo)[i] = srcL[i];
            }
        }
        __syncthreads();

        float acc1[1][8][4];
#pragma unroll
        for (int b = 0; b < 8; b++)
#pragma unroll
            for (int c = 0; c < 4; c++) acc1[0][b][c] = 0.f;

#pragma unroll
        for (int ks = 0; ks < 8; ks++)
            mma_step<1, 8>(acc1, Ahi, Alo, KP128, Whi, Wlo, KP128,
                           m0, n0, ks * 16, ks * 16, g, t);
        __syncthreads();     // done reading Wm1 half; W buffer reusable

        // epilogue B1: h3half = relu(acc1 + bm1) -> W buffer rows 0..63
        {
            int rr = m0 + g;
#pragma unroll
            for (int nf = 0; nf < 8; nf++) {
                int colL = n0 + nf * 8 + t * 2;          // local 0..127
                float2 bv = *(const float2*)&bm1[nb * 128 + colL];
                float v0 = fmaxf(acc1[0][nf][0] + bv.x, 0.f);
                float v1 = fmaxf(acc1[0][nf][1] + bv.y, 0.f);
                float v2 = fmaxf(acc1[0][nf][2] + bv.x, 0.f);
                float v3 = fmaxf(acc1[0][nf][3] + bv.y, 0.f);
                __nv_bfloat16 h0, l0, h1, l1; split2(v0, h0, l0); split2(v1, h1, l1);
                *(unsigned*)&Whi[rr * KP128 + colL] = pack_bf2(h0, h1);
                *(unsigned*)&Wlo[rr * KP128 + colL] = pack_bf2(l0, l1);
                split2(v2, h0, l0); split2(v3, h1, l1);
                *(unsigned*)&Whi[(rr + 8) * KP128 + colL] = pack_bf2(h0, h1);
                *(unsigned*)&Wlo[(rr + 8) * KP128 + colL] = pack_bf2(l0, l1);
            }
        }
        // stage Wm2 k-half nb into W rows 64..103
        for (int i = tid; i < 40 * 16; i += 256) {
            int n = i >> 4, q = i & 15;
            *(uint4*)&Whi[(64 + n) * KP128 + q * 8] =
                *(const uint4*)&g_m2hi[n * KP256 + nb * 128 + q * 8];
            *(uint4*)&Wlo[(64 + n) * KP128 + q * 8] =
                *(const uint4*)&g_m2lo[n * KP256 + nb * 128 + q * 8];
        }
        __syncthreads();

        // m2 partial: warps 0-3, A = h3half (W rows 0..63), B = Wm2 (W rows 64+)
        if (w < 4) {
            int m0b = w * 16;
#pragma unroll
            for (int ks = 0; ks < 8; ks++)
                mma_step<1, 5>(acc2, Whi, Wlo, KP128,
                               Whi + 64 * KP128, Wlo + 64 * KP128, KP128,
                               m0b, 0, ks * 16, ks * 16, g, t);
        }
    }

    // ---------------- final epilogue: out = acc2 + bm2 ----------------------
    if (w < 4) {
        int r0 = node0 + w * 16 + g;
#pragma unroll
        for (int nf = 0; nf < 5; nf++) {
            int col = nf * 8 + t * 2;
            float2 bv = *(const float2*)&bm2[col];
            if (r0 < N_NODES) {
                float2 o = make_float2(acc2[0][nf][0] + bv.x, acc2[0][nf][1] + bv.y);
                *(float2*)&out[(size_t)r0 * D_OUT + col] = o;
            }
            if (r0 + 8 < N_NODES) {
                float2 o = make_float2(acc2[0][nf][2] + bv.x, acc2[0][nf][3] + bv.y);
                *(float2*)&out[(size_t)(r0 + 8) * D_OUT + col] = o;
            }
        }
    }
}

// ---------------- launch -----------------------------------------------------
extern "C" void kernel_launch(void* const* d_in, const int* in_sizes, int n_in,
                              void* d_out, int out_size) {
    const float* feat = (const float*)d_in[0];
    const int*   ei   = (const int*)d_in[1];     // int32 (JAX x64 disabled)
    const float* W1   = (const float*)d_in[2];
    const float* b1   = (const float*)d_in[3];
    const float* W2   = (const float*)d_in[4];
    const float* b2   = (const float*)d_in[5];
    const float* Wm1  = (const float*)d_in[6];
    const float* bm1  = (const float*)d_in[7];
    const float* Wm2  = (const float*)d_in[8];
    const float* bm2  = (const float*)d_in[9];
    float* out = (float*)d_out;

    cudaFuncSetAttribute(l1_mma_kernel, cudaFuncAttributeMaxDynamicSharedMemorySize, L1_SMEM);
    cudaFuncSetAttribute(fused_l2_mlp_kernel, cudaFuncAttributeMaxDynamicSharedMemorySize, F_SMEM);

    // CSR build
    zero_cnt_kernel<<<(N_NODES + 255) / 256, 256>>>();
    hist_kernel<<<(N_EDGES + 255) / 256, 256>>>(ei);
    scan1_kernel<<<NB_SCAN, 256>>>();
    scan2_kernel<<<1, 512>>>();
    scan3_kernel<<<NB_SCAN, 256>>>();
    fill_kernel<<<(N_EDGES + 255) / 256, 256>>>(ei);

    // pre-split static operands
    split_feat_kernel<<<(N_NODES * D_IN / 2 + 255) / 256, 256>>>(feat);
    split_w_kernel<<<(92160 + 255) / 256, 256>>>(W1, W2, Wm1, Wm2);

    // layer 1
    gather1_kernel<<<(N_NODES * 32 + 255) / 256, 256>>>(feat);
    l1_mma_kernel<<<(N_NODES + 63) / 64, 256, L1_SMEM>>>(b1);

    // layer 2 + MLP (fused)
    gather2_kernel<<<(N_NODES * 32 + 255) / 256, 256>>>();
    fused_l2_mlp_kernel<<<(N_NODES + 63) / 64, 256, F_SMEM>>>(b2, bm1, bm2, out);
}